// round 15
// baseline (speedup 1.0000x reference)
#include <cuda_runtime.h>
#include <cuda_fp16.h>
#include <math.h>
#include <stdint.h>

// ---------------- problem constants ----------------
#define BB   4
#define SS   512
#define HH   512
#define NHH  8
#define TT   3
#define DHH  64
#define DTS  170
#define BS   (BB*SS)             // 2048
#define BSS  (BB*SS*SS)          // 1,048,576
#define EPS  1e-5f

// mask lookup table
#define NTAB   4096
#define M0MAX  5.6400f
#define TABENT (NTAB+1)
#define TABSZ  (3*2*TABENT + 3)

// ---------------- scratch layout (fp32 region, float slots) ----------------
#define OFF_MASK     ((size_t)0)
#define OFF_QKV      (OFF_MASK + (size_t)3*BSS)
#define OFF_ATTNO    (OFF_QKV + (size_t)3*BS*1536)
#define OFF_COMB     (OFF_ATTNO + (size_t)3*BS*HH)
#define OFF_MACT     (OFF_COMB + (size_t)BS*1536)
#define OFF_WEIGHTED (OFF_MACT + (size_t)BS*HH)
#define OFF_SA       (OFF_WEIGHTED + (size_t)BS*HH)
#define OFF_H1       (OFF_SA + (size_t)BS*HH)
#define OFF_FFO      (OFF_H1 + (size_t)BS*HH)
#define OFF_H2       (OFF_FFO + (size_t)BS*HH)
#define OFF_OP       (OFF_H2 + (size_t)BS*HH)
#define OFF_TAB      (OFF_OP + (size_t)BS*HH)
#define OFF_F32END   (((OFF_TAB + (size_t)TABSZ) + 3) & ~(size_t)3)

// ---------------- half region (u32 word slots) ----------------
#define OFFW_XH       OFF_F32END
#define OFFW_WHQKV    (OFFW_XH + (size_t)524288)
#define OFFW_WHATTN   (OFFW_WHQKV + (size_t)1179648)
#define OFFW_WHMIX1   (OFFW_WHATTN + (size_t)393216)
#define OFFW_WHELQKV  (OFFW_WHMIX1 + (size_t)393216)
#define OFFW_WHELOUT  (OFFW_WHELQKV + (size_t)393216)
#define OFFW_WHFF1    (OFFW_WHELOUT + (size_t)131072)
#define OFFW_WHFF2    (OFFW_WHFF1 + (size_t)524288)
#define OFFW_WHOP     (OFFW_WHFF2 + (size_t)524288)
#define OFFW_ATTNOH   (OFFW_WHOP + (size_t)131072)
#define OFFW_COMBH    (OFFW_ATTNOH + (size_t)1572864)
#define OFFW_WEIGHTEDH (OFFW_COMBH + (size_t)1572864)
#define OFFW_H1H      (OFFW_WEIGHTEDH + (size_t)524288)
#define OFFW_FFH      (OFFW_H1H + (size_t)524288)
#define OFFW_H2H      (OFFW_FFH + (size_t)2097152)
#define OFFW_QKVH     (OFFW_H2H + (size_t)524288)
#define SCRATCH_FLOATS (OFFW_QKVH + (size_t)4718592)

__device__ __align__(16) float g_scratch[SCRATCH_FLOATS];

// ---------------- helpers ----------------
__device__ __forceinline__ float gelu_exact(float x) {
    return 0.5f * x * (1.0f + erff(x * 0.70710678118654752f));
}
__device__ __forceinline__ float warp_sum(float x) {
    #pragma unroll
    for (int o = 16; o > 0; o >>= 1) x += __shfl_xor_sync(0xffffffffu, x, o);
    return x;
}
__device__ __forceinline__ float to_tf32(float x) {
    uint32_t u;
    asm("cvt.rna.tf32.f32 %0, %1;" : "=r"(u) : "f"(x));
    return __uint_as_float(u);
}
__device__ __forceinline__ void mma_tf32(float* c, const float* a, const float* b) {
    asm volatile(
        "mma.sync.aligned.m16n8k8.row.col.f32.tf32.tf32.f32 "
        "{%0,%1,%2,%3}, {%4,%5,%6,%7}, {%8,%9}, {%0,%1,%2,%3};\n"
        : "+f"(c[0]), "+f"(c[1]), "+f"(c[2]), "+f"(c[3])
        : "r"(__float_as_uint(a[0])), "r"(__float_as_uint(a[1])),
          "r"(__float_as_uint(a[2])), "r"(__float_as_uint(a[3])),
          "r"(__float_as_uint(b[0])), "r"(__float_as_uint(b[1])));
}
__device__ __forceinline__ void mma_f16(float* c, const uint32_t* a, const uint32_t* b) {
    asm volatile(
        "mma.sync.aligned.m16n8k16.row.col.f32.f16.f16.f32 "
        "{%0,%1,%2,%3}, {%4,%5,%6,%7}, {%8,%9}, {%0,%1,%2,%3};\n"
        : "+f"(c[0]), "+f"(c[1]), "+f"(c[2]), "+f"(c[3])
        : "r"(a[0]), "r"(a[1]), "r"(a[2]), "r"(a[3]),
          "r"(b[0]), "r"(b[1]));
}
__device__ __forceinline__ uint32_t pack_h2(float lo, float hi) {
    __half2 h = __floats2half2_rn(lo, hi);
    return *reinterpret_cast<uint32_t*>(&h);
}
__device__ __forceinline__ void cp_async16(uint32_t dst, const void* src) {
    asm volatile("cp.async.ca.shared.global [%0], [%1], 16;\n" :: "r"(dst), "l"(src));
}
#define CP_COMMIT() asm volatile("cp.async.commit_group;\n" ::: "memory")
#define CP_WAIT0()  asm volatile("cp.async.wait_group 0;\n" ::: "memory")
#define CP_WAIT1()  asm volatile("cp.async.wait_group 1;\n" ::: "memory")

// ---------------- operand pre-convert: fp32 -> half ----------------
__global__ void cvt_kernel(const float* __restrict__ x,
                           const float* __restrict__ qkvW,  const float* __restrict__ attnW,
                           const float* __restrict__ mix1W, const float* __restrict__ elqkvW,
                           const float* __restrict__ eloutW,const float* __restrict__ ff1W,
                           const float* __restrict__ ff2W,  const float* __restrict__ opW,
                           uint32_t* __restrict__ baseW)
{
    const uint32_t TOTW = 4194304u;
    for (uint32_t w = blockIdx.x*blockDim.x + threadIdx.x; w < TOTW; w += gridDim.x*blockDim.x) {
        const float* src; uint32_t rel, N; uint32_t* dst;
        if      (w < 524288u)  { src = x;      rel = w;            N = 1;    dst = baseW + OFFW_XH; }
        else if (w < 1703936u) { src = qkvW;   rel = w - 524288u;  N = 1536; dst = baseW + OFFW_WHQKV; }
        else if (w < 2097152u) { src = attnW;  rel = w - 1703936u; N = 512;  dst = baseW + OFFW_WHATTN; }
        else if (w < 2490368u) { src = mix1W;  rel = w - 2097152u; N = 512;  dst = baseW + OFFW_WHMIX1; }
        else if (w < 2883584u) { src = elqkvW; rel = w - 2490368u; N = 1536; dst = baseW + OFFW_WHELQKV; }
        else if (w < 3014656u) { src = eloutW; rel = w - 2883584u; N = 512;  dst = baseW + OFFW_WHELOUT; }
        else if (w < 3538944u) { src = ff1W;   rel = w - 3014656u; N = 2048; dst = baseW + OFFW_WHFF1; }
        else if (w < 4063232u) { src = ff2W;   rel = w - 3538944u; N = 512;  dst = baseW + OFFW_WHFF2; }
        else                   { src = opW;    rel = w - 4063232u; N = 512;  dst = baseW + OFFW_WHOP; }
        uint32_t p = rel / N, n = rel - p*N;
        dst[rel] = pack_h2(src[(size_t)(2*p)*N + n], src[(size_t)(2*p+1)*N + n]);
    }
}

// ---------------- mask table build ----------------
__global__ void tab_kernel(const float* __restrict__ enc_W,
                           const float* __restrict__ enc_b,
                           const float* __restrict__ enc_g,
                           const float* __restrict__ enc_be,
                           float* __restrict__ tab)
{
    int w = (blockIdx.x * blockDim.x + threadIdx.x) >> 5;
    int lane = threadIdx.x & 31;
    const int NE = 3 * 2 * TABENT;
    if (w >= NE + 3) return;
    int i; float dir, mag;
    if (w < NE) {
        i = w / (2 * TABENT);
        int r = w - i * (2 * TABENT);
        int d = r / TABENT;
        int j = r - d * TABENT;
        dir = d ? 1.f : -1.f;
        float m0 = (float)j * (M0MAX / NTAB);
        float sc = (i == 0) ? 1.f : ((i == 1) ? 0.1f : 0.01f);
        mag = m0 * sc;
    } else {
        i = w - NE; dir = 0.f; mag = 0.f;
    }
    const float* W0 = enc_W + (size_t)(i*2+0)*DTS;
    const float* W1 = enc_W + (size_t)(i*2+1)*DTS;
    const float* bb = enc_b + (size_t)i*DTS;
    const float* gg = enc_g + (size_t)i*DTS;
    const float* be = enc_be + (size_t)i*DTS;

    float e[6];
    float s = 0.f, ss = 0.f;
    #pragma unroll
    for (int j2 = 0; j2 < 6; j2++) {
        int d = lane + 32*j2;
        float v = 0.f;
        if (d < DTS) v = dir*W0[d] + mag*W1[d] + bb[d];
        e[j2] = v; s += v; ss += v*v;
    }
    s  = warp_sum(s);
    ss = warp_sum(ss);
    float mean = s * (1.f/DTS);
    float var  = ss * (1.f/DTS) - mean*mean;
    float rs = rsqrtf(var + EPS);
    float gs = 0.f;
    #pragma unroll
    for (int j2 = 0; j2 < 6; j2++) {
        int d = lane + 32*j2;
        if (d < DTS) {
            float y = (e[j2] - mean) * rs * gg[d] + be[d];
            gs += gelu_exact(y);
        }
    }
    gs = warp_sum(gs);
    if (lane == 0) tab[w] = gs * (1.f/DTS);
}

// ---------------- mask fill via table interpolation ----------------
__global__ void maskfill_kernel(const float* __restrict__ ts,
                                const float* __restrict__ tab,
                                float* __restrict__ masks)
{
    int idx = blockIdx.x * blockDim.x + threadIdx.x;
    if (idx >= BSS) return;
    int b = idx >> 18;
    int q = (idx >> 9) & 511;
    int k = idx & 511;
    float dt = ts[(b << 9) + q] - ts[(b << 9) + k];
    if (dt == 0.f) {
        #pragma unroll
        for (int i = 0; i < TT; i++)
            masks[(size_t)i*BSS + idx] = tab[3*2*TABENT + i];
    } else {
        int d = dt > 0.f ? 1 : 0;
        float m0 = log1pf(fabsf(dt) * (1.f/3600.f));
        float t = m0 * ((float)NTAB / M0MAX);
        t = fminf(t, (float)NTAB - 1e-3f);
        int j = (int)t;
        float f = t - (float)j;
        #pragma unroll
        for (int i = 0; i < TT; i++) {
            const float* tb = tab + (size_t)(i*2 + d) * TABENT;
            float a = tb[j];
            masks[(size_t)i*BSS + idx] = a + f * (tb[j+1] - a);
        }
    }
}

// ---------------- fp16 GEMM, cp.async, BK=32, 3-stage, DYNAMIC smem ----------------
// A: plain half [M][lda], staged [row][20 words] (16 used). B: pre-interleaved [K/2][ldbW].
// OH: 0 = fp32 C only; 1 = fp32 C + half Ch; 2 = half Ch only.
#define G_SAW 20
#define G_ASTGW (128*G_SAW)
#define G_BNP(BN) ((BN) == 128 ? 136 : 72)
#define G_BSTGW(BN) (16*G_BNP(BN))
#define G_SMEM_BYTES(BN) ((3*G_ASTGW + 3*G_BSTGW(BN))*4)

template<int BN, int GELU, int OH>
__global__ __launch_bounds__(256)
void gemm_ca(const uint32_t* __restrict__ AhW, int lda,
             const uint32_t* __restrict__ BwW, int ldbW,
             const float* __restrict__ bias0,
             float* __restrict__ C0, int ldc,
             uint32_t* __restrict__ ChW, int ldch,
             int K,
             size_t sAzW, size_t sBzW, size_t sCz, size_t sChzW, size_t sbz)
{
    constexpr int SAW = G_SAW;
    constexpr int BNP = G_BNP(BN);
    constexpr int WN  = BN / 4;
    constexpr int NT2 = WN / 8;
    constexpr int ASTGW = G_ASTGW;
    constexpr int BSTGW = G_BSTGW(BN);

    extern __shared__ __align__(16) uint32_t gsm[];
    uint32_t* sA = gsm;                 // [3][ASTGW]
    uint32_t* sB = gsm + 3*ASTGW;       // [3][BSTGW]

    const int tid  = threadIdx.x;
    const int lane = tid & 31;
    const int warp = tid >> 5;
    const int wm = warp & 1;
    const int wn = warp >> 1;
    const int g = lane >> 2;
    const int c = lane & 3;

    const int bm = blockIdx.y * 128;
    const int bn = blockIdx.x * BN;
    const int z  = blockIdx.z;

    const float* bias = bias0 + (size_t)z * sbz;

    const int arow = tid >> 1, ahalf = tid & 1;
    const char* aSrc = (const char*)(AhW + (size_t)z*sAzW)
                       + ((size_t)(bm + arow) * lda) * 2 + ahalf * 32;
    const uint32_t saBase = (uint32_t)__cvta_generic_to_shared(sA);
    const uint32_t sbBase = (uint32_t)__cvta_generic_to_shared(sB);
    const uint32_t aDstOff = (uint32_t)((arow*SAW + ahalf*8) * 4);

    int bbp, bwo; bool bact2;
    if (BN == 128) { bbp = tid >> 4; bwo = (tid & 15) * 8; bact2 = true; }
    else           { bbp = tid >> 4; bwo = (tid & 15) * 4; bact2 = false; }
    const uint32_t* bSrc = BwW + (size_t)z*sBzW + (size_t)bbp*ldbW + bn + bwo;
    const uint32_t bDstOff = (uint32_t)((bbp*BNP + bwo) * 4);

    float acc[4][NT2][4];
    #pragma unroll
    for (int i = 0; i < 4; i++)
        #pragma unroll
        for (int j = 0; j < NT2; j++)
            #pragma unroll
            for (int q = 0; q < 4; q++) acc[i][j][q] = 0.f;

    auto issue = [&](int s) {
        const int stg = s % 3;
        const uint32_t ad = saBase + (uint32_t)(stg*ASTGW*4) + aDstOff;
        const char* as = aSrc + (size_t)s*64;
        cp_async16(ad, as);
        cp_async16(ad + 16, as + 16);
        const uint32_t bd = sbBase + (uint32_t)(stg*BSTGW*4) + bDstOff;
        const uint32_t* bs = bSrc + (size_t)s*16*ldbW;
        cp_async16(bd, bs);
        if (bact2) cp_async16(bd + 16, bs + 4);
    };

    const int nstage = K / 32;
    issue(0); CP_COMMIT();
    if (nstage > 1) { issue(1); CP_COMMIT(); }

    for (int s = 0; s < nstage; s++) {
        if (s + 1 < nstage) { CP_WAIT1(); } else { CP_WAIT0(); }
        __syncthreads();
        if (s + 2 < nstage) { issue(s + 2); CP_COMMIT(); }

        const int stg = s % 3;
        const uint32_t* A_ = sA + stg*ASTGW;
        const uint32_t* B_ = sB + stg*BSTGW;

        #pragma unroll
        for (int kk = 0; kk < 2; kk++) {
            const int kb = kk * 8;
            uint32_t af[4][4];
            #pragma unroll
            for (int mt = 0; mt < 4; mt++) {
                const int rb = (wm*64 + mt*16 + g)*SAW + kb;
                af[mt][0] = A_[rb + c];
                af[mt][1] = A_[rb + 8*SAW + c];
                af[mt][2] = A_[rb + c + 4];
                af[mt][3] = A_[rb + 8*SAW + c + 4];
            }
            uint32_t bf[NT2][2];
            #pragma unroll
            for (int nt = 0; nt < NT2; nt++) {
                const int n0 = wn*WN + nt*8 + g;
                bf[nt][0] = B_[(kb + c)*BNP + n0];
                bf[nt][1] = B_[(kb + c + 4)*BNP + n0];
            }
            #pragma unroll
            for (int mt = 0; mt < 4; mt++)
                #pragma unroll
                for (int nt = 0; nt < NT2; nt++)
                    mma_f16(acc[mt][nt], af[mt], bf[nt]);
        }
    }

    float* C = C0 + (size_t)z * sCz;
    uint32_t* Ch = ChW + (size_t)z * sChzW;
    #pragma unroll
    for (int mt = 0; mt < 4; mt++) {
        const int row = bm + wm*64 + mt*16 + g;
        #pragma unroll
        for (int nt = 0; nt < NT2; nt++) {
            const int col = bn + wn*WN + nt*8 + c*2;
            float2 bb = *(const float2*)(bias + col);
            float v00 = acc[mt][nt][0] + bb.x, v01 = acc[mt][nt][1] + bb.y;
            float v10 = acc[mt][nt][2] + bb.x, v11 = acc[mt][nt][3] + bb.y;
            if (GELU) {
                v00 = gelu_exact(v00); v01 = gelu_exact(v01);
                v10 = gelu_exact(v10); v11 = gelu_exact(v11);
            }
            if (OH != 2) {
                *(float2*)(C + (size_t)row*ldc + col) = make_float2(v00, v01);
                *(float2*)(C + (size_t)(row+8)*ldc + col) = make_float2(v10, v11);
            }
            if (OH >= 1) {
                Ch[((size_t)row*ldch + col) >> 1]     = pack_h2(v00, v01);
                Ch[((size_t)(row+8)*ldch + col) >> 1] = pack_h2(v10, v11);
            }
        }
    }
}

// ---------------- fused flash attention: fp16 QK^T, tf32 PV, double-buffered K and V ----------------
// smem (words): KH0 [64][36] | KH1 [64][36] (Q first) | V0 fp32 [64][68] | V1 fp32 [64][68]
#define KHS 36
#define KHTILE (64*KHS)            // 2304 words
#define VOFFW  (2*KHTILE)          // 4608
#define FVS 68
#define VTILE (64*FVS)             // 4352 words
#define FLASH_SMEM_BYTES ((2*KHTILE + 2*VTILE)*4)   // 53248 B

__global__ __launch_bounds__(128, 4)
void flash_kernel(const float* __restrict__ qkvb,          // fp32 (V)
                  const uint32_t* __restrict__ qkhW,       // half qkv (Q,K)
                  const float* __restrict__ maskb,
                  float* __restrict__ attnob,
                  uint32_t* __restrict__ attnohW)
{
    extern __shared__ uint32_t fsw[];
    float* fsm = (float*)fsw;

    const int qt = blockIdx.x;
    const int bh = blockIdx.y;
    const int t  = blockIdx.z;
    const int b = bh >> 3, h = bh & 7;
    const int tid = threadIdx.x;
    const int lane = tid & 31, warp = tid >> 5;
    const int g = lane >> 2, c = lane & 3;
    const int r0 = warp*16 + g, r1 = r0 + 8;

    const size_t qbase = (size_t)t*BS*1536 + (size_t)b*SS*1536 + h*DHH;
    const uint32_t* QhW = qkhW + (qbase >> 1);
    const uint32_t* KhW = QhW + (HH >> 1);
    const float* Vp = qkvb + qbase + 2*HH;
    const float* Mp = maskb ? (maskb + (size_t)t*BSS + (size_t)b*SS*SS + (size_t)(qt*64)*SS)
                            : nullptr;
    const size_t obase = (size_t)t*BS*HH + (size_t)b*SS*HH + (size_t)(qt*64)*HH + h*DHH;
    float* Op = attnob + obase;
    uint32_t* OhW = attnohW + (obase >> 1);

    const int srow = tid >> 1;
    const int shalfH = (tid & 1) * 16;
    const int shalfV = (tid & 1) * 32;
    const uint32_t smemBase = (uint32_t)__cvta_generic_to_shared(fsw);

    auto stageH = [&](const uint32_t* srcW, int tile, uint32_t dstTileW) {
        const uint32_t* src = srcW + (size_t)(tile*64 + srow)*768 + shalfH;
        uint32_t dst = smemBase + (dstTileW + (uint32_t)(srow*KHS + shalfH)) * 4;
        #pragma unroll
        for (int j = 0; j < 4; j++) cp_async16(dst + j*16, src + j*4);
    };
    auto stageV = [&](int tile, int buf) {
        const float* vsrc = Vp + (size_t)(tile*64 + srow)*1536 + shalfV;
        uint32_t vdst = smemBase + (uint32_t)(VOFFW + buf*VTILE + srow*FVS + shalfV) * 4;
        #pragma unroll
        for (int j = 0; j < 8; j++) cp_async16(vdst + j*16, vsrc + j*4);
    };

    // prologue: Q -> KH1 region; K(0) -> KH0; V(0) -> V0
    {
        stageH(QhW, qt, (uint32_t)KHTILE);
        stageH(KhW, 0, 0u);
        stageV(0, 0);
        CP_COMMIT();
        CP_WAIT0();
        __syncthreads();
    }

    uint32_t qf[4][4];
    {
        const uint32_t* sQ = fsw + KHTILE;
        #pragma unroll
        for (int j = 0; j < 4; j++) {
            qf[j][0] = sQ[r0*KHS + 8*j + c];
            qf[j][1] = sQ[r1*KHS + 8*j + c];
            qf[j][2] = sQ[r0*KHS + 8*j + c + 4];
            qf[j][3] = sQ[r1*KHS + 8*j + c + 4];
        }
    }
    __syncthreads();   // Q reads done before kt=0 stages into KH1

    float of[8][4];
    #pragma unroll
    for (int nt = 0; nt < 8; nt++)
        #pragma unroll
        for (int q = 0; q < 4; q++) of[nt][q] = 0.f;
    float mA = -1e30f, lA = 0.f, mB = -1e30f, lB = 0.f;

    for (int kt = 0; kt < 8; kt++) {
        const int cur = kt & 1;
        const bool more = (kt + 1 < 8);
        if (more) {
            stageH(KhW, kt + 1, (uint32_t)((cur ^ 1)*KHTILE));
            stageV(kt + 1, cur ^ 1);
            CP_COMMIT();
        }

        const uint32_t* sK = fsw + cur*KHTILE;
        const float* sV = fsm + VOFFW + cur*VTILE;

        // ---- scores: fp16 m16n8k16 ----
        float sc[8][4];
        #pragma unroll
        for (int nt = 0; nt < 8; nt++)
            sc[nt][0] = sc[nt][1] = sc[nt][2] = sc[nt][3] = 0.f;
        #pragma unroll
        for (int j = 0; j < 4; j++) {
            #pragma unroll
            for (int nt = 0; nt < 8; nt++) {
                const uint32_t* kp = sK + (nt*8 + g)*KHS + 8*j;
                uint32_t bf[2] = { kp[c], kp[c + 4] };
                mma_f16(sc[nt], qf[j], bf);
            }
        }
        if (Mp) {
            const float* m0p = Mp + (size_t)r0*SS + kt*64 + 2*c;
            const float* m1p = Mp + (size_t)r1*SS + kt*64 + 2*c;
            #pragma unroll
            for (int nt = 0; nt < 8; nt++) {
                float2 u = *(const float2*)(m0p + nt*8);
                float2 v = *(const float2*)(m1p + nt*8);
                sc[nt][0] = sc[nt][0]*0.125f + u.x;
                sc[nt][1] = sc[nt][1]*0.125f + u.y;
                sc[nt][2] = sc[nt][2]*0.125f + v.x;
                sc[nt][3] = sc[nt][3]*0.125f + v.y;
            }
        } else {
            #pragma unroll
            for (int nt = 0; nt < 8; nt++) {
                sc[nt][0] *= 0.125f; sc[nt][1] *= 0.125f;
                sc[nt][2] *= 0.125f; sc[nt][3] *= 0.125f;
            }
        }
        // ---- online softmax ----
        float aMax = -1e30f, bMax = -1e30f;
        #pragma unroll
        for (int nt = 0; nt < 8; nt++) {
            aMax = fmaxf(aMax, fmaxf(sc[nt][0], sc[nt][1]));
            bMax = fmaxf(bMax, fmaxf(sc[nt][2], sc[nt][3]));
        }
        aMax = fmaxf(aMax, __shfl_xor_sync(0xffffffffu, aMax, 1));
        aMax = fmaxf(aMax, __shfl_xor_sync(0xffffffffu, aMax, 2));
        bMax = fmaxf(bMax, __shfl_xor_sync(0xffffffffu, bMax, 1));
        bMax = fmaxf(bMax, __shfl_xor_sync(0xffffffffu, bMax, 2));
        float mnA = fmaxf(mA, aMax), mnB = fmaxf(mB, bMax);
        float alA = __expf(mA - mnA), alB = __expf(mB - mnB);
        mA = mnA; mB = mnB;
        float sumA = 0.f, sumB = 0.f;
        #pragma unroll
        for (int nt = 0; nt < 8; nt++) {
            sc[nt][0] = __expf(sc[nt][0] - mnA); sumA += sc[nt][0];
            sc[nt][1] = __expf(sc[nt][1] - mnA); sumA += sc[nt][1];
            sc[nt][2] = __expf(sc[nt][2] - mnB); sumB += sc[nt][2];
            sc[nt][3] = __expf(sc[nt][3] - mnB); sumB += sc[nt][3];
        }
        sumA += __shfl_xor_sync(0xffffffffu, sumA, 1);
        sumA += __shfl_xor_sync(0xffffffffu, sumA, 2);
        sumB += __shfl_xor_sync(0xffffffffu, sumB, 1);
        sumB += __shfl_xor_sync(0xffffffffu, sumB, 2);
        lA = lA*alA + sumA;
        lB = lB*alB + sumB;
        #pragma unroll
        for (int nt = 0; nt < 8; nt++) {
            of[nt][0] *= alA; of[nt][1] *= alA;
            of[nt][2] *= alB; of[nt][3] *= alB;
        }

        // ---- PV (tf32): V(kt) already resident ----
        #pragma unroll
        for (int ks = 0; ks < 8; ks++) {
            float af[4] = { to_tf32(sc[ks][0]), to_tf32(sc[ks][2]),
                            to_tf32(sc[ks][1]), to_tf32(sc[ks][3]) };
            #pragma unroll
            for (int nt = 0; nt < 8; nt++) {
                const float* vp = sV + (ks*8 + 2*c)*FVS + nt*8 + g;
                float bf[2] = { to_tf32(vp[0]), to_tf32(vp[FVS]) };
                mma_tf32(of[nt], af, bf);
            }
        }

        if (more) { CP_WAIT0(); }
        __syncthreads();   // (kt+1) tiles visible; all warps done with cur before kt+2 overwrites
    }

    const float invA = 1.f / lA, invB = 1.f / lB;
    #pragma unroll
    for (int nt = 0; nt < 8; nt++) {
        const int col = nt*8 + 2*c;
        float o00 = of[nt][0]*invA, o01 = of[nt][1]*invA;
        float o10 = of[nt][2]*invB, o11 = of[nt][3]*invB;
        *(float2*)(Op + (size_t)r0*HH + col) = make_float2(o00, o01);
        *(float2*)(Op + (size_t)r1*HH + col) = make_float2(o10, o11);
        OhW[((size_t)r0*HH + col) >> 1] = pack_h2(o00, o01);
        OhW[((size_t)r1*HH + col) >> 1] = pack_h2(o10, o11);
    }
}

// ---------------- LayerNorm over 512 (+residual, +gelu, +optional half copy) ----------------
__global__ void ln_kernel(const float* __restrict__ in, const float* __restrict__ res,
                          const float* __restrict__ g, const float* __restrict__ be,
                          float* __restrict__ out, __half* __restrict__ outh, int do_gelu)
{
    __shared__ float red[4];
    int row = blockIdx.x, tid = threadIdx.x;
    const float* ip = in + (size_t)row*HH;
    const float* rp = res ? (res + (size_t)row*HH) : nullptr;
    float v[4]; float s = 0.f;
    #pragma unroll
    for (int j = 0; j < 4; j++) {
        float x = ip[tid + 128*j];
        if (rp) x += rp[tid + 128*j];
        v[j] = x; s += x;
    }
    s = warp_sum(s);
    if ((tid & 31) == 0) red[tid >> 5] = s;
    __syncthreads();
    float mean = (red[0]+red[1]+red[2]+red[3]) * (1.f/HH);
    __syncthreads();
    float ss = 0.f;
    #pragma unroll
    for (int j = 0; j < 4; j++) { float d = v[j] - mean; ss += d*d; }
    ss = warp_sum(ss);
    if ((tid & 31) == 0) red[tid >> 5] = ss;
    __syncthreads();
    float var = (red[0]+red[1]+red[2]+red[3]) * (1.f/HH);
    float rs = rsqrtf(var + EPS);
    float* op = out + (size_t)row*HH;
    __half* oh = outh ? (outh + (size_t)row*HH) : nullptr;
    #pragma unroll
    for (int j = 0; j < 4; j++) {
        int cc = tid + 128*j;
        float y = (v[j] - mean) * rs * g[cc] + be[cc];
        if (do_gelu) y = gelu_exact(y);
        op[cc] = y;
        if (oh) oh[cc] = __float2half_rn(y);
    }
}

// ---------------- mixer ----------------
__global__ void mix_kernel(const float* __restrict__ mact, const float* __restrict__ W2,
                           const float* __restrict__ b2, const float* __restrict__ comb,
                           float* __restrict__ weighted, __half* __restrict__ weightedh)
{
    __shared__ float sl[3][4];
    __shared__ float smix[3];
    int row = blockIdx.x, tid = threadIdx.x;
    const float* mrow = mact + (size_t)row*HH;
    float l0 = 0.f, l1 = 0.f, l2 = 0.f;
    for (int d = tid; d < HH; d += 128) {
        float m = mrow[d];
        l0 += m * W2[d*3+0];
        l1 += m * W2[d*3+1];
        l2 += m * W2[d*3+2];
    }
    l0 = warp_sum(l0); l1 = warp_sum(l1); l2 = warp_sum(l2);
    int w = tid >> 5;
    if ((tid & 31) == 0) { sl[0][w] = l0; sl[1][w] = l1; sl[2][w] = l2; }
    __syncthreads();
    if (tid == 0) {
        float a0 = sl[0][0]+sl[0][1]+sl[0][2]+sl[0][3] + b2[0];
        float a1 = sl[1][0]+sl[1][1]+sl[1][2]+sl[1][3] + b2[1];
        float a2 = sl[2][0]+sl[2][1]+sl[2][2]+sl[2][3] + b2[2];
        float mx = fmaxf(a0, fmaxf(a1, a2));
        float e0 = expf(a0-mx), e1 = expf(a1-mx), e2 = expf(a2-mx);
        float inv = 1.f / (e0+e1+e2);
        smix[0] = e0*inv; smix[1] = e1*inv; smix[2] = e2*inv;
    }
    __syncthreads();
    float m0 = smix[0], m1 = smix[1], m2 = smix[2];
    const float* crow = comb + (size_t)row*(3*HH);
    float* wrow = weighted + (size_t)row*HH;
    __half* whrow = weightedh + (size_t)row*HH;
    for (int cc = tid; cc < HH; cc += 128) {
        float v = m0*crow[cc] + m1*crow[HH + cc] + m2*crow[2*HH + cc];
        wrow[cc] = v;
        whrow[cc] = __float2half_rn(v);
    }
}

// ---------------- launch ----------------
extern "C" void kernel_launch(void* const* d_in, const int* in_sizes, int n_in,
                              void* d_out, int out_size)
{
    const float* x          = (const float*)d_in[0];
    const float* ts         = (const float*)d_in[1];
    const float* enc_W      = (const float*)d_in[2];
    const float* enc_b      = (const float*)d_in[3];
    const float* enc_ln_g   = (const float*)d_in[4];
    const float* enc_ln_b   = (const float*)d_in[5];
    const float* qkv_W      = (const float*)d_in[6];
    const float* qkv_b      = (const float*)d_in[7];
    const float* attn_out_W = (const float*)d_in[8];
    const float* attn_out_b = (const float*)d_in[9];
    const float* mixer_W1   = (const float*)d_in[10];
    const float* mixer_b1   = (const float*)d_in[11];
    const float* mixer_ln_g = (const float*)d_in[12];
    const float* mixer_ln_b = (const float*)d_in[13];
    const float* mixer_W2   = (const float*)d_in[14];
    const float* mixer_b2   = (const float*)d_in[15];
    const float* el_qkv_W   = (const float*)d_in[16];
    const float* el_qkv_b   = (const float*)d_in[17];
    const float* el_out_W   = (const float*)d_in[18];
    const float* el_out_b   = (const float*)d_in[19];
    const float* el_ln1_g   = (const float*)d_in[20];
    const float* el_ln1_b   = (const float*)d_in[21];
    const float* el_ff_W1   = (const float*)d_in[22];
    const float* el_ff_b1   = (const float*)d_in[23];
    const float* el_ff_W2   = (const float*)d_in[24];
    const float* el_ff_b2   = (const float*)d_in[25];
    const float* el_ln2_g   = (const float*)d_in[26];
    const float* el_ln2_b   = (const float*)d_in[27];
    const float* op_W       = (const float*)d_in[28];
    const float* op_b       = (const float*)d_in[29];
    const float* op_ln_g    = (const float*)d_in[30];
    const float* op_ln_b    = (const float*)d_in[31];
    float* out = (float*)d_out;

    float* base = nullptr;
    cudaGetSymbolAddress((void**)&base, g_scratch);
    uint32_t* baseW = (uint32_t*)base;

    float* maskv    = base + OFF_MASK;
    float* qkv      = base + OFF_QKV;
    float* attno    = base + OFF_ATTNO;
    float* comb     = base + OFF_COMB;
    float* mact     = base + OFF_MACT;
    float* weighted = base + OFF_WEIGHTED;
    float* sa       = base + OFF_SA;
    float* h1       = base + OFF_H1;
    float* ffo      = base + OFF_FFO;
    float* h2       = base + OFF_H2;
    float* opb      = base + OFF_OP;
    float* tab      = base + OFF_TAB;

    uint32_t* xh      = baseW + OFFW_XH;
    uint32_t* whqkv   = baseW + OFFW_WHQKV;
    uint32_t* whattn  = baseW + OFFW_WHATTN;
    uint32_t* whmix1  = baseW + OFFW_WHMIX1;
    uint32_t* whelqkv = baseW + OFFW_WHELQKV;
    uint32_t* whelout = baseW + OFFW_WHELOUT;
    uint32_t* whff1   = baseW + OFFW_WHFF1;
    uint32_t* whff2   = baseW + OFFW_WHFF2;
    uint32_t* whop    = baseW + OFFW_WHOP;
    uint32_t* attnoh  = baseW + OFFW_ATTNOH;
    uint32_t* combh   = baseW + OFFW_COMBH;
    uint32_t* weightedh = baseW + OFFW_WEIGHTEDH;
    uint32_t* h1h     = baseW + OFFW_H1H;
    uint32_t* ffh     = baseW + OFFW_FFH;
    uint32_t* h2h     = baseW + OFFW_H2H;
    uint32_t* qkvh    = baseW + OFFW_QKVH;

    // raise dynamic smem caps (idempotent)
    cudaFuncSetAttribute(flash_kernel, cudaFuncAttributeMaxDynamicSharedMemorySize, FLASH_SMEM_BYTES);
    cudaFuncSetAttribute(gemm_ca<128,0,1>, cudaFuncAttributeMaxDynamicSharedMemorySize, G_SMEM_BYTES(128));
    cudaFuncSetAttribute(gemm_ca<128,1,2>, cudaFuncAttributeMaxDynamicSharedMemorySize, G_SMEM_BYTES(128));
    cudaFuncSetAttribute(gemm_ca<64,0,1>,  cudaFuncAttributeMaxDynamicSharedMemorySize, G_SMEM_BYTES(64));
    cudaFuncSetAttribute(gemm_ca<64,0,0>,  cudaFuncAttributeMaxDynamicSharedMemorySize, G_SMEM_BYTES(64));

    // 0. operand pre-convert (x + all weights)
    cvt_kernel<<<4096, 256>>>(x, qkv_W, attn_out_W, mixer_W1, el_qkv_W, el_out_W,
                              el_ff_W1, el_ff_W2, op_W, baseW);

    // 1. mask tables + fill
    {
        int nwarp = 3*2*TABENT + 3;
        int nblk = (nwarp*32 + 255) / 256;
        tab_kernel<<<nblk, 256>>>(enc_W, enc_b, enc_ln_g, enc_ln_b, tab);
        maskfill_kernel<<<(BSS + 255)/256, 256>>>(ts, tab, maskv);
    }

    // 2. per-timescale QKV (batched z=3, fp32 + half out) + fused attention + attn_out
    gemm_ca<128,0,1><<<dim3(12,16,3), 256, G_SMEM_BYTES(128)>>>(xh, HH, whqkv, 1536, qkv_b, qkv, 1536,
                                             qkvh, 1536, HH,
                                             (size_t)0, (size_t)256*1536, (size_t)BS*1536,
                                             (size_t)BS*1536/2, (size_t)1536);
    flash_kernel<<<dim3(8, BB*NHH, 3), 128, FLASH_SMEM_BYTES>>>(qkv, qkvh, maskv, attno, attnoh);
    gemm_ca<64,0,1><<<dim3(8,16,3), 256, G_SMEM_BYTES(64)>>>(attnoh, HH, whattn, HH, attn_out_b, comb, 1536,
                                           combh, 1536, HH,
                                           (size_t)BS*HH/2, (size_t)256*512, (size_t)HH, (size_t)HH/2, (size_t)HH);

    // 3. time mixer
    gemm_ca<64,0,0><<<dim3(8,16,1), 256, G_SMEM_BYTES(64)>>>(combh, 1536, whmix1, HH, mixer_b1, mact, HH,
                                           baseW, 0, 1536,
                                           (size_t)0,(size_t)0,(size_t)0,(size_t)0,(size_t)0);
    ln_kernel<<<BS, 128>>>(mact, nullptr, mixer_ln_g, mixer_ln_b, mact, nullptr, 1);
    mix_kernel<<<BS, 128>>>(mact, mixer_W2, mixer_b2, comb, weighted, (__half*)weightedh);

    // 4. transformer encoder layer (post-norm)
    gemm_ca<128,0,1><<<dim3(12,16,1), 256, G_SMEM_BYTES(128)>>>(weightedh, HH, whelqkv, 1536, el_qkv_b, qkv, 1536,
                                             qkvh, 1536, HH,
                                             (size_t)0,(size_t)0,(size_t)0,(size_t)0,(size_t)0);
    flash_kernel<<<dim3(8, BB*NHH, 1), 128, FLASH_SMEM_BYTES>>>(qkv, qkvh, nullptr, attno, attnoh);
    gemm_ca<64,0,0><<<dim3(8,16,1), 256, G_SMEM_BYTES(64)>>>(attnoh, HH, whelout, HH, el_out_b, sa, HH,
                                           baseW, 0, HH,
                                           (size_t)0,(size_t)0,(size_t)0,(size_t)0,(size_t)0);
    ln_kernel<<<BS, 128>>>(sa, weighted, el_ln1_g, el_ln1_b, h1, (__half*)h1h, 0);
    gemm_ca<128,1,2><<<dim3(16,16,1), 256, G_SMEM_BYTES(128)>>>(h1h, HH, whff1, 2048, el_ff_b1, nullptr, 2048,
                                             ffh, 2048, HH,
                                             (size_t)0,(size_t)0,(size_t)0,(size_t)0,(size_t)0);
    gemm_ca<64,0,0><<<dim3(8,16,1), 256, G_SMEM_BYTES(64)>>>(ffh, 2048, whff2, HH, el_ff_b2, ffo, HH,
                                           baseW, 0, 2048,
                                           (size_t)0,(size_t)0,(size_t)0,(size_t)0,(size_t)0);
    ln_kernel<<<BS, 128>>>(ffo, h1, el_ln2_g, el_ln2_b, h2, (__half*)h2h, 0);

    // 5. output projection + LN
    gemm_ca<64,0,0><<<dim3(8,16,1), 256, G_SMEM_BYTES(64)>>>(h2h, HH, whop, HH, op_b, opb, HH,
                                           baseW, 0, HH,
                                           (size_t)0,(size_t)0,(size_t)0,(size_t)0,(size_t)0);
    ln_kernel<<<BS, 128>>>(opb, nullptr, op_ln_g, op_ln_b, out, nullptr, 0);
}

// round 16
// speedup vs baseline: 1.0607x; 1.0607x over previous
#include <cuda_runtime.h>
#include <cuda_fp16.h>
#include <math.h>
#include <stdint.h>

// ---------------- problem constants ----------------
#define BB   4
#define SS   512
#define HH   512
#define NHH  8
#define TT   3
#define DHH  64
#define DTS  170
#define BS   (BB*SS)             // 2048
#define BSS  (BB*SS*SS)          // 1,048,576
#define EPS  1e-5f

// mask lookup table
#define NTAB   4096
#define M0MAX  5.6400f
#define TABENT (NTAB+1)
#define TABSZ  (3*2*TABENT + 3)

// ---------------- scratch layout (fp32 region, float slots) ----------------
#define OFF_MASK     ((size_t)0)
#define OFF_QKV      (OFF_MASK + (size_t)3*BSS)
#define OFF_ATTNO    (OFF_QKV + (size_t)3*BS*1536)
#define OFF_COMB     (OFF_ATTNO + (size_t)3*BS*HH)
#define OFF_MACT     (OFF_COMB + (size_t)BS*1536)
#define OFF_WEIGHTED (OFF_MACT + (size_t)BS*HH)
#define OFF_SA       (OFF_WEIGHTED + (size_t)BS*HH)
#define OFF_H1       (OFF_SA + (size_t)BS*HH)
#define OFF_FFO      (OFF_H1 + (size_t)BS*HH)
#define OFF_H2       (OFF_FFO + (size_t)BS*HH)
#define OFF_OP       (OFF_H2 + (size_t)BS*HH)
#define OFF_TAB      (OFF_OP + (size_t)BS*HH)
#define OFF_F32END   (((OFF_TAB + (size_t)TABSZ) + 3) & ~(size_t)3)

// ---------------- half region (u32 word slots) ----------------
#define OFFW_XH       OFF_F32END
#define OFFW_WHQKV    (OFFW_XH + (size_t)524288)
#define OFFW_WHATTN   (OFFW_WHQKV + (size_t)1179648)
#define OFFW_WHMIX1   (OFFW_WHATTN + (size_t)393216)
#define OFFW_WHELQKV  (OFFW_WHMIX1 + (size_t)393216)
#define OFFW_WHELOUT  (OFFW_WHELQKV + (size_t)393216)
#define OFFW_WHFF1    (OFFW_WHELOUT + (size_t)131072)
#define OFFW_WHFF2    (OFFW_WHFF1 + (size_t)524288)
#define OFFW_WHOP     (OFFW_WHFF2 + (size_t)524288)
#define OFFW_ATTNOH   (OFFW_WHOP + (size_t)131072)
#define OFFW_COMBH    (OFFW_ATTNOH + (size_t)1572864)
#define OFFW_WEIGHTEDH (OFFW_COMBH + (size_t)1572864)
#define OFFW_H1H      (OFFW_WEIGHTEDH + (size_t)524288)
#define OFFW_FFH      (OFFW_H1H + (size_t)524288)
#define OFFW_H2H      (OFFW_FFH + (size_t)2097152)
#define OFFW_QKVH     (OFFW_H2H + (size_t)524288)
#define SCRATCH_FLOATS (OFFW_QKVH + (size_t)4718592)

__device__ __align__(16) float g_scratch[SCRATCH_FLOATS];

// ---------------- helpers ----------------
__device__ __forceinline__ float gelu_exact(float x) {
    return 0.5f * x * (1.0f + erff(x * 0.70710678118654752f));
}
__device__ __forceinline__ float warp_sum(float x) {
    #pragma unroll
    for (int o = 16; o > 0; o >>= 1) x += __shfl_xor_sync(0xffffffffu, x, o);
    return x;
}
__device__ __forceinline__ float to_tf32(float x) {
    uint32_t u;
    asm("cvt.rna.tf32.f32 %0, %1;" : "=r"(u) : "f"(x));
    return __uint_as_float(u);
}
__device__ __forceinline__ void mma_tf32(float* c, const float* a, const float* b) {
    asm volatile(
        "mma.sync.aligned.m16n8k8.row.col.f32.tf32.tf32.f32 "
        "{%0,%1,%2,%3}, {%4,%5,%6,%7}, {%8,%9}, {%0,%1,%2,%3};\n"
        : "+f"(c[0]), "+f"(c[1]), "+f"(c[2]), "+f"(c[3])
        : "r"(__float_as_uint(a[0])), "r"(__float_as_uint(a[1])),
          "r"(__float_as_uint(a[2])), "r"(__float_as_uint(a[3])),
          "r"(__float_as_uint(b[0])), "r"(__float_as_uint(b[1])));
}
__device__ __forceinline__ void mma_f16(float* c, const uint32_t* a, const uint32_t* b) {
    asm volatile(
        "mma.sync.aligned.m16n8k16.row.col.f32.f16.f16.f32 "
        "{%0,%1,%2,%3}, {%4,%5,%6,%7}, {%8,%9}, {%0,%1,%2,%3};\n"
        : "+f"(c[0]), "+f"(c[1]), "+f"(c[2]), "+f"(c[3])
        : "r"(a[0]), "r"(a[1]), "r"(a[2]), "r"(a[3]),
          "r"(b[0]), "r"(b[1]));
}
__device__ __forceinline__ uint32_t pack_h2(float lo, float hi) {
    __half2 h = __floats2half2_rn(lo, hi);
    return *reinterpret_cast<uint32_t*>(&h);
}
__device__ __forceinline__ void cp_async16(uint32_t dst, const void* src) {
    asm volatile("cp.async.ca.shared.global [%0], [%1], 16;\n" :: "r"(dst), "l"(src));
}
#define CP_COMMIT() asm volatile("cp.async.commit_group;\n" ::: "memory")
#define CP_WAIT0()  asm volatile("cp.async.wait_group 0;\n" ::: "memory")
#define CP_WAIT1()  asm volatile("cp.async.wait_group 1;\n" ::: "memory")
#define CP_WAIT2()  asm volatile("cp.async.wait_group 2;\n" ::: "memory")

// ---------------- operand pre-convert: fp32 -> half ----------------
__global__ void cvt_kernel(const float* __restrict__ x,
                           const float* __restrict__ qkvW,  const float* __restrict__ attnW,
                           const float* __restrict__ mix1W, const float* __restrict__ elqkvW,
                           const float* __restrict__ eloutW,const float* __restrict__ ff1W,
                           const float* __restrict__ ff2W,  const float* __restrict__ opW,
                           uint32_t* __restrict__ baseW)
{
    const uint32_t TOTW = 4194304u;
    for (uint32_t w = blockIdx.x*blockDim.x + threadIdx.x; w < TOTW; w += gridDim.x*blockDim.x) {
        const float* src; uint32_t rel, N; uint32_t* dst;
        if      (w < 524288u)  { src = x;      rel = w;            N = 1;    dst = baseW + OFFW_XH; }
        else if (w < 1703936u) { src = qkvW;   rel = w - 524288u;  N = 1536; dst = baseW + OFFW_WHQKV; }
        else if (w < 2097152u) { src = attnW;  rel = w - 1703936u; N = 512;  dst = baseW + OFFW_WHATTN; }
        else if (w < 2490368u) { src = mix1W;  rel = w - 2097152u; N = 512;  dst = baseW + OFFW_WHMIX1; }
        else if (w < 2883584u) { src = elqkvW; rel = w - 2490368u; N = 1536; dst = baseW + OFFW_WHELQKV; }
        else if (w < 3014656u) { src = eloutW; rel = w - 2883584u; N = 512;  dst = baseW + OFFW_WHELOUT; }
        else if (w < 3538944u) { src = ff1W;   rel = w - 3014656u; N = 2048; dst = baseW + OFFW_WHFF1; }
        else if (w < 4063232u) { src = ff2W;   rel = w - 3538944u; N = 512;  dst = baseW + OFFW_WHFF2; }
        else                   { src = opW;    rel = w - 4063232u; N = 512;  dst = baseW + OFFW_WHOP; }
        uint32_t p = rel / N, n = rel - p*N;
        dst[rel] = pack_h2(src[(size_t)(2*p)*N + n], src[(size_t)(2*p+1)*N + n]);
    }
}

// ---------------- mask table build ----------------
__global__ void tab_kernel(const float* __restrict__ enc_W,
                           const float* __restrict__ enc_b,
                           const float* __restrict__ enc_g,
                           const float* __restrict__ enc_be,
                           float* __restrict__ tab)
{
    int w = (blockIdx.x * blockDim.x + threadIdx.x) >> 5;
    int lane = threadIdx.x & 31;
    const int NE = 3 * 2 * TABENT;
    if (w >= NE + 3) return;
    int i; float dir, mag;
    if (w < NE) {
        i = w / (2 * TABENT);
        int r = w - i * (2 * TABENT);
        int d = r / TABENT;
        int j = r - d * TABENT;
        dir = d ? 1.f : -1.f;
        float m0 = (float)j * (M0MAX / NTAB);
        float sc = (i == 0) ? 1.f : ((i == 1) ? 0.1f : 0.01f);
        mag = m0 * sc;
    } else {
        i = w - NE; dir = 0.f; mag = 0.f;
    }
    const float* W0 = enc_W + (size_t)(i*2+0)*DTS;
    const float* W1 = enc_W + (size_t)(i*2+1)*DTS;
    const float* bb = enc_b + (size_t)i*DTS;
    const float* gg = enc_g + (size_t)i*DTS;
    const float* be = enc_be + (size_t)i*DTS;

    float e[6];
    float s = 0.f, ss = 0.f;
    #pragma unroll
    for (int j2 = 0; j2 < 6; j2++) {
        int d = lane + 32*j2;
        float v = 0.f;
        if (d < DTS) v = dir*W0[d] + mag*W1[d] + bb[d];
        e[j2] = v; s += v; ss += v*v;
    }
    s  = warp_sum(s);
    ss = warp_sum(ss);
    float mean = s * (1.f/DTS);
    float var  = ss * (1.f/DTS) - mean*mean;
    float rs = rsqrtf(var + EPS);
    float gs = 0.f;
    #pragma unroll
    for (int j2 = 0; j2 < 6; j2++) {
        int d = lane + 32*j2;
        if (d < DTS) {
            float y = (e[j2] - mean) * rs * gg[d] + be[d];
            gs += gelu_exact(y);
        }
    }
    gs = warp_sum(gs);
    if (lane == 0) tab[w] = gs * (1.f/DTS);
}

// ---------------- mask fill via table interpolation ----------------
__global__ void maskfill_kernel(const float* __restrict__ ts,
                                const float* __restrict__ tab,
                                float* __restrict__ masks)
{
    int idx = blockIdx.x * blockDim.x + threadIdx.x;
    if (idx >= BSS) return;
    int b = idx >> 18;
    int q = (idx >> 9) & 511;
    int k = idx & 511;
    float dt = ts[(b << 9) + q] - ts[(b << 9) + k];
    if (dt == 0.f) {
        #pragma unroll
        for (int i = 0; i < TT; i++)
            masks[(size_t)i*BSS + idx] = tab[3*2*TABENT + i];
    } else {
        int d = dt > 0.f ? 1 : 0;
        float m0 = log1pf(fabsf(dt) * (1.f/3600.f));
        float t = m0 * ((float)NTAB / M0MAX);
        t = fminf(t, (float)NTAB - 1e-3f);
        int j = (int)t;
        float f = t - (float)j;
        #pragma unroll
        for (int i = 0; i < TT; i++) {
            const float* tb = tab + (size_t)(i*2 + d) * TABENT;
            float a = tb[j];
            masks[(size_t)i*BSS + idx] = a + f * (tb[j+1] - a);
        }
    }
}

// ---------------- fp16 GEMM with cp.async staging, BK=16, 4-stage (R13 proven) ----------------
// OH: 0 = fp32 C only; 1 = fp32 C + half Ch; 2 = half Ch only.
template<int BN, int GELU, int OH>
__global__ __launch_bounds__(256)
void gemm_ca(const uint32_t* __restrict__ AhW, int lda,
             const uint32_t* __restrict__ BwW, int ldbW,
             const float* __restrict__ bias0,
             float* __restrict__ C0, int ldc,
             uint32_t* __restrict__ ChW, int ldch,
             int K,
             size_t sAzW, size_t sBzW, size_t sCz, size_t sChzW, size_t sbz)
{
    constexpr int SAW = 12;
    constexpr int BNP = (BN == 128) ? 136 : 72;
    constexpr int WN  = BN / 4;
    constexpr int NT2 = WN / 8;
    constexpr int ASTGW = 128*SAW;
    constexpr int BSTGW = 8*BNP;

    __shared__ __align__(16) uint32_t sA[4*ASTGW];
    __shared__ __align__(16) uint32_t sB[4*BSTGW];

    const int tid  = threadIdx.x;
    const int lane = tid & 31;
    const int warp = tid >> 5;
    const int wm = warp & 1;
    const int wn = warp >> 1;
    const int g = lane >> 2;
    const int c = lane & 3;

    const int bm = blockIdx.y * 128;
    const int bn = blockIdx.x * BN;
    const int z  = blockIdx.z;

    const float* bias = bias0 + (size_t)z * sbz;

    const int arow = tid >> 1, ahalf = tid & 1;
    const char* aSrc = (const char*)(AhW + (size_t)z*sAzW)
                       + ((size_t)(bm + arow) * lda) * 2 + ahalf * 16;
    const uint32_t saBase = (uint32_t)__cvta_generic_to_shared(sA);
    const uint32_t sbBase = (uint32_t)__cvta_generic_to_shared(sB);
    const uint32_t aDstOff = (uint32_t)((arow*SAW + ahalf*4) * 4);

    int bbp, bch; bool bact;
    if (BN == 128) { bbp = tid >> 5; bch = tid & 31; bact = true; }
    else           { bbp = tid >> 4; bch = tid & 15; bact = (tid < 128); }
    const uint32_t* bSrc = BwW + (size_t)z*sBzW + (size_t)bbp*ldbW + bn + bch*4;
    const uint32_t bDstOff = (uint32_t)((bbp*BNP + bch*4) * 4);

    float acc[4][NT2][4];
    #pragma unroll
    for (int i = 0; i < 4; i++)
        #pragma unroll
        for (int j = 0; j < NT2; j++)
            #pragma unroll
            for (int q = 0; q < 4; q++) acc[i][j][q] = 0.f;

    auto issue = [&](int s) {
        const int stg = s & 3;
        cp_async16(saBase + (uint32_t)(stg*ASTGW*4) + aDstOff, aSrc + (size_t)s*32);
        if (bact) cp_async16(sbBase + (uint32_t)(stg*BSTGW*4) + bDstOff,
                             (const void*)(bSrc + (size_t)s*8*ldbW));
    };

    const int nstage = K / 16;
    issue(0); CP_COMMIT();
    if (nstage > 1) { issue(1); CP_COMMIT(); }
    if (nstage > 2) { issue(2); CP_COMMIT(); }

    for (int s = 0; s < nstage; s++) {
        const int rem = nstage - 1 - s;
        if (rem >= 2) { CP_WAIT2(); } else if (rem == 1) { CP_WAIT1(); } else { CP_WAIT0(); }
        __syncthreads();
        if (s + 3 < nstage) { issue(s + 3); CP_COMMIT(); }

        const int stg = s & 3;
        const uint32_t* A_ = sA + stg*ASTGW;
        const uint32_t* B_ = sB + stg*BSTGW;

        uint32_t af[4][4];
        #pragma unroll
        for (int mt = 0; mt < 4; mt++) {
            const int rb = (wm*64 + mt*16 + g)*SAW;
            af[mt][0] = A_[rb + c];
            af[mt][1] = A_[rb + 8*SAW + c];
            af[mt][2] = A_[rb + c + 4];
            af[mt][3] = A_[rb + 8*SAW + c + 4];
        }
        uint32_t bf[NT2][2];
        #pragma unroll
        for (int nt = 0; nt < NT2; nt++) {
            const int n0 = wn*WN + nt*8 + g;
            bf[nt][0] = B_[c*BNP + n0];
            bf[nt][1] = B_[(c+4)*BNP + n0];
        }
        #pragma unroll
        for (int mt = 0; mt < 4; mt++)
            #pragma unroll
            for (int nt = 0; nt < NT2; nt++)
                mma_f16(acc[mt][nt], af[mt], bf[nt]);
    }

    float* C = C0 + (size_t)z * sCz;
    uint32_t* Ch = ChW + (size_t)z * sChzW;
    #pragma unroll
    for (int mt = 0; mt < 4; mt++) {
        const int row = bm + wm*64 + mt*16 + g;
        #pragma unroll
        for (int nt = 0; nt < NT2; nt++) {
            const int col = bn + wn*WN + nt*8 + c*2;
            float2 bb = *(const float2*)(bias + col);
            float v00 = acc[mt][nt][0] + bb.x, v01 = acc[mt][nt][1] + bb.y;
            float v10 = acc[mt][nt][2] + bb.x, v11 = acc[mt][nt][3] + bb.y;
            if (GELU) {
                v00 = gelu_exact(v00); v01 = gelu_exact(v01);
                v10 = gelu_exact(v10); v11 = gelu_exact(v11);
            }
            if (OH != 2) {
                *(float2*)(C + (size_t)row*ldc + col) = make_float2(v00, v01);
                *(float2*)(C + (size_t)(row+8)*ldc + col) = make_float2(v10, v11);
            }
            if (OH >= 1) {
                Ch[((size_t)row*ldch + col) >> 1]     = pack_h2(v00, v01);
                Ch[((size_t)(row+8)*ldch + col) >> 1] = pack_h2(v10, v11);
            }
        }
    }
}

// ---------------- fused flash attention: fp16 QK^T, tf32 PV, double-buffered K and V (R15) ----------------
// smem (words): KH0 [64][36] | KH1 [64][36] (Q first) | V0 fp32 [64][68] | V1 fp32 [64][68]
#define KHS 36
#define KHTILE (64*KHS)            // 2304 words
#define VOFFW  (2*KHTILE)          // 4608
#define FVS 68
#define VTILE (64*FVS)             // 4352 words
#define FLASH_SMEM_BYTES ((2*KHTILE + 2*VTILE)*4)   // 53248 B

__global__ __launch_bounds__(128, 4)
void flash_kernel(const float* __restrict__ qkvb,          // fp32 (V)
                  const uint32_t* __restrict__ qkhW,       // half qkv (Q,K)
                  const float* __restrict__ maskb,
                  float* __restrict__ attnob,
                  uint32_t* __restrict__ attnohW)
{
    extern __shared__ uint32_t fsw[];
    float* fsm = (float*)fsw;

    const int qt = blockIdx.x;
    const int bh = blockIdx.y;
    const int t  = blockIdx.z;
    const int b = bh >> 3, h = bh & 7;
    const int tid = threadIdx.x;
    const int lane = tid & 31, warp = tid >> 5;
    const int g = lane >> 2, c = lane & 3;
    const int r0 = warp*16 + g, r1 = r0 + 8;

    const size_t qbase = (size_t)t*BS*1536 + (size_t)b*SS*1536 + h*DHH;
    const uint32_t* QhW = qkhW + (qbase >> 1);
    const uint32_t* KhW = QhW + (HH >> 1);
    const float* Vp = qkvb + qbase + 2*HH;
    const float* Mp = maskb ? (maskb + (size_t)t*BSS + (size_t)b*SS*SS + (size_t)(qt*64)*SS)
                            : nullptr;
    const size_t obase = (size_t)t*BS*HH + (size_t)b*SS*HH + (size_t)(qt*64)*HH + h*DHH;
    float* Op = attnob + obase;
    uint32_t* OhW = attnohW + (obase >> 1);

    const int srow = tid >> 1;
    const int shalfH = (tid & 1) * 16;
    const int shalfV = (tid & 1) * 32;
    const uint32_t smemBase = (uint32_t)__cvta_generic_to_shared(fsw);

    auto stageH = [&](const uint32_t* srcW, int tile, uint32_t dstTileW) {
        const uint32_t* src = srcW + (size_t)(tile*64 + srow)*768 + shalfH;
        uint32_t dst = smemBase + (dstTileW + (uint32_t)(srow*KHS + shalfH)) * 4;
        #pragma unroll
        for (int j = 0; j < 4; j++) cp_async16(dst + j*16, src + j*4);
    };
    auto stageV = [&](int tile, int buf) {
        const float* vsrc = Vp + (size_t)(tile*64 + srow)*1536 + shalfV;
        uint32_t vdst = smemBase + (uint32_t)(VOFFW + buf*VTILE + srow*FVS + shalfV) * 4;
        #pragma unroll
        for (int j = 0; j < 8; j++) cp_async16(vdst + j*16, vsrc + j*4);
    };

    // prologue: Q -> KH1 region; K(0) -> KH0; V(0) -> V0
    {
        stageH(QhW, qt, (uint32_t)KHTILE);
        stageH(KhW, 0, 0u);
        stageV(0, 0);
        CP_COMMIT();
        CP_WAIT0();
        __syncthreads();
    }

    uint32_t qf[4][4];
    {
        const uint32_t* sQ = fsw + KHTILE;
        #pragma unroll
        for (int j = 0; j < 4; j++) {
            qf[j][0] = sQ[r0*KHS + 8*j + c];
            qf[j][1] = sQ[r1*KHS + 8*j + c];
            qf[j][2] = sQ[r0*KHS + 8*j + c + 4];
            qf[j][3] = sQ[r1*KHS + 8*j + c + 4];
        }
    }
    __syncthreads();   // Q reads done before kt=0 stages into KH1

    float of[8][4];
    #pragma unroll
    for (int nt = 0; nt < 8; nt++)
        #pragma unroll
        for (int q = 0; q < 4; q++) of[nt][q] = 0.f;
    float mA = -1e30f, lA = 0.f, mB = -1e30f, lB = 0.f;

    for (int kt = 0; kt < 8; kt++) {
        const int cur = kt & 1;
        const bool more = (kt + 1 < 8);
        if (more) {
            stageH(KhW, kt + 1, (uint32_t)((cur ^ 1)*KHTILE));
            stageV(kt + 1, cur ^ 1);
            CP_COMMIT();
        }

        const uint32_t* sK = fsw + cur*KHTILE;
        const float* sV = fsm + VOFFW + cur*VTILE;

        // ---- scores: fp16 m16n8k16 ----
        float sc[8][4];
        #pragma unroll
        for (int nt = 0; nt < 8; nt++)
            sc[nt][0] = sc[nt][1] = sc[nt][2] = sc[nt][3] = 0.f;
        #pragma unroll
        for (int j = 0; j < 4; j++) {
            #pragma unroll
            for (int nt = 0; nt < 8; nt++) {
                const uint32_t* kp = sK + (nt*8 + g)*KHS + 8*j;
                uint32_t bf[2] = { kp[c], kp[c + 4] };
                mma_f16(sc[nt], qf[j], bf);
            }
        }
        if (Mp) {
            const float* m0p = Mp + (size_t)r0*SS + kt*64 + 2*c;
            const float* m1p = Mp + (size_t)r1*SS + kt*64 + 2*c;
            #pragma unroll
            for (int nt = 0; nt < 8; nt++) {
                float2 u = *(const float2*)(m0p + nt*8);
                float2 v = *(const float2*)(m1p + nt*8);
                sc[nt][0] = sc[nt][0]*0.125f + u.x;
                sc[nt][1] = sc[nt][1]*0.125f + u.y;
                sc[nt][2] = sc[nt][2]*0.125f + v.x;
                sc[nt][3] = sc[nt][3]*0.125f + v.y;
            }
        } else {
            #pragma unroll
            for (int nt = 0; nt < 8; nt++) {
                sc[nt][0] *= 0.125f; sc[nt][1] *= 0.125f;
                sc[nt][2] *= 0.125f; sc[nt][3] *= 0.125f;
            }
        }
        // ---- online softmax ----
        float aMax = -1e30f, bMax = -1e30f;
        #pragma unroll
        for (int nt = 0; nt < 8; nt++) {
            aMax = fmaxf(aMax, fmaxf(sc[nt][0], sc[nt][1]));
            bMax = fmaxf(bMax, fmaxf(sc[nt][2], sc[nt][3]));
        }
        aMax = fmaxf(aMax, __shfl_xor_sync(0xffffffffu, aMax, 1));
        aMax = fmaxf(aMax, __shfl_xor_sync(0xffffffffu, aMax, 2));
        bMax = fmaxf(bMax, __shfl_xor_sync(0xffffffffu, bMax, 1));
        bMax = fmaxf(bMax, __shfl_xor_sync(0xffffffffu, bMax, 2));
        float mnA = fmaxf(mA, aMax), mnB = fmaxf(mB, bMax);
        float alA = __expf(mA - mnA), alB = __expf(mB - mnB);
        mA = mnA; mB = mnB;
        float sumA = 0.f, sumB = 0.f;
        #pragma unroll
        for (int nt = 0; nt < 8; nt++) {
            sc[nt][0] = __expf(sc[nt][0] - mnA); sumA += sc[nt][0];
            sc[nt][1] = __expf(sc[nt][1] - mnA); sumA += sc[nt][1];
            sc[nt][2] = __expf(sc[nt][2] - mnB); sumB += sc[nt][2];
            sc[nt][3] = __expf(sc[nt][3] - mnB); sumB += sc[nt][3];
        }
        sumA += __shfl_xor_sync(0xffffffffu, sumA, 1);
        sumA += __shfl_xor_sync(0xffffffffu, sumA, 2);
        sumB += __shfl_xor_sync(0xffffffffu, sumB, 1);
        sumB += __shfl_xor_sync(0xffffffffu, sumB, 2);
        lA = lA*alA + sumA;
        lB = lB*alB + sumB;
        #pragma unroll
        for (int nt = 0; nt < 8; nt++) {
            of[nt][0] *= alA; of[nt][1] *= alA;
            of[nt][2] *= alB; of[nt][3] *= alB;
        }

        // ---- PV (tf32): V(kt) already resident ----
        #pragma unroll
        for (int ks = 0; ks < 8; ks++) {
            float af[4] = { to_tf32(sc[ks][0]), to_tf32(sc[ks][2]),
                            to_tf32(sc[ks][1]), to_tf32(sc[ks][3]) };
            #pragma unroll
            for (int nt = 0; nt < 8; nt++) {
                const float* vp = sV + (ks*8 + 2*c)*FVS + nt*8 + g;
                float bf[2] = { to_tf32(vp[0]), to_tf32(vp[FVS]) };
                mma_tf32(of[nt], af, bf);
            }
        }

        if (more) { CP_WAIT0(); }
        __syncthreads();   // (kt+1) tiles visible; all warps done with cur before kt+2 overwrites
    }

    const float invA = 1.f / lA, invB = 1.f / lB;
    #pragma unroll
    for (int nt = 0; nt < 8; nt++) {
        const int col = nt*8 + 2*c;
        float o00 = of[nt][0]*invA, o01 = of[nt][1]*invA;
        float o10 = of[nt][2]*invB, o11 = of[nt][3]*invB;
        *(float2*)(Op + (size_t)r0*HH + col) = make_float2(o00, o01);
        *(float2*)(Op + (size_t)r1*HH + col) = make_float2(o10, o11);
        OhW[((size_t)r0*HH + col) >> 1] = pack_h2(o00, o01);
        OhW[((size_t)r1*HH + col) >> 1] = pack_h2(o10, o11);
    }
}

// ---------------- LayerNorm over 512 (+residual, +gelu, +optional half copy) ----------------
__global__ void ln_kernel(const float* __restrict__ in, const float* __restrict__ res,
                          const float* __restrict__ g, const float* __restrict__ be,
                          float* __restrict__ out, __half* __restrict__ outh, int do_gelu)
{
    __shared__ float red[4];
    int row = blockIdx.x, tid = threadIdx.x;
    const float* ip = in + (size_t)row*HH;
    const float* rp = res ? (res + (size_t)row*HH) : nullptr;
    float v[4]; float s = 0.f;
    #pragma unroll
    for (int j = 0; j < 4; j++) {
        float x = ip[tid + 128*j];
        if (rp) x += rp[tid + 128*j];
        v[j] = x; s += x;
    }
    s = warp_sum(s);
    if ((tid & 31) == 0) red[tid >> 5] = s;
    __syncthreads();
    float mean = (red[0]+red[1]+red[2]+red[3]) * (1.f/HH);
    __syncthreads();
    float ss = 0.f;
    #pragma unroll
    for (int j = 0; j < 4; j++) { float d = v[j] - mean; ss += d*d; }
    ss = warp_sum(ss);
    if ((tid & 31) == 0) red[tid >> 5] = ss;
    __syncthreads();
    float var = (red[0]+red[1]+red[2]+red[3]) * (1.f/HH);
    float rs = rsqrtf(var + EPS);
    float* op = out + (size_t)row*HH;
    __half* oh = outh ? (outh + (size_t)row*HH) : nullptr;
    #pragma unroll
    for (int j = 0; j < 4; j++) {
        int cc = tid + 128*j;
        float y = (v[j] - mean) * rs * g[cc] + be[cc];
        if (do_gelu) y = gelu_exact(y);
        op[cc] = y;
        if (oh) oh[cc] = __float2half_rn(y);
    }
}

// ---------------- mixer ----------------
__global__ void mix_kernel(const float* __restrict__ mact, const float* __restrict__ W2,
                           const float* __restrict__ b2, const float* __restrict__ comb,
                           float* __restrict__ weighted, __half* __restrict__ weightedh)
{
    __shared__ float sl[3][4];
    __shared__ float smix[3];
    int row = blockIdx.x, tid = threadIdx.x;
    const float* mrow = mact + (size_t)row*HH;
    float l0 = 0.f, l1 = 0.f, l2 = 0.f;
    for (int d = tid; d < HH; d += 128) {
        float m = mrow[d];
        l0 += m * W2[d*3+0];
        l1 += m * W2[d*3+1];
        l2 += m * W2[d*3+2];
    }
    l0 = warp_sum(l0); l1 = warp_sum(l1); l2 = warp_sum(l2);
    int w = tid >> 5;
    if ((tid & 31) == 0) { sl[0][w] = l0; sl[1][w] = l1; sl[2][w] = l2; }
    __syncthreads();
    if (tid == 0) {
        float a0 = sl[0][0]+sl[0][1]+sl[0][2]+sl[0][3] + b2[0];
        float a1 = sl[1][0]+sl[1][1]+sl[1][2]+sl[1][3] + b2[1];
        float a2 = sl[2][0]+sl[2][1]+sl[2][2]+sl[2][3] + b2[2];
        float mx = fmaxf(a0, fmaxf(a1, a2));
        float e0 = expf(a0-mx), e1 = expf(a1-mx), e2 = expf(a2-mx);
        float inv = 1.f / (e0+e1+e2);
        smix[0] = e0*inv; smix[1] = e1*inv; smix[2] = e2*inv;
    }
    __syncthreads();
    float m0 = smix[0], m1 = smix[1], m2 = smix[2];
    const float* crow = comb + (size_t)row*(3*HH);
    float* wrow = weighted + (size_t)row*HH;
    __half* whrow = weightedh + (size_t)row*HH;
    for (int cc = tid; cc < HH; cc += 128) {
        float v = m0*crow[cc] + m1*crow[HH + cc] + m2*crow[2*HH + cc];
        wrow[cc] = v;
        whrow[cc] = __float2half_rn(v);
    }
}

// ---------------- launch ----------------
extern "C" void kernel_launch(void* const* d_in, const int* in_sizes, int n_in,
                              void* d_out, int out_size)
{
    const float* x          = (const float*)d_in[0];
    const float* ts         = (const float*)d_in[1];
    const float* enc_W      = (const float*)d_in[2];
    const float* enc_b      = (const float*)d_in[3];
    const float* enc_ln_g   = (const float*)d_in[4];
    const float* enc_ln_b   = (const float*)d_in[5];
    const float* qkv_W      = (const float*)d_in[6];
    const float* qkv_b      = (const float*)d_in[7];
    const float* attn_out_W = (const float*)d_in[8];
    const float* attn_out_b = (const float*)d_in[9];
    const float* mixer_W1   = (const float*)d_in[10];
    const float* mixer_b1   = (const float*)d_in[11];
    const float* mixer_ln_g = (const float*)d_in[12];
    const float* mixer_ln_b = (const float*)d_in[13];
    const float* mixer_W2   = (const float*)d_in[14];
    const float* mixer_b2   = (const float*)d_in[15];
    const float* el_qkv_W   = (const float*)d_in[16];
    const float* el_qkv_b   = (const float*)d_in[17];
    const float* el_out_W   = (const float*)d_in[18];
    const float* el_out_b   = (const float*)d_in[19];
    const float* el_ln1_g   = (const float*)d_in[20];
    const float* el_ln1_b   = (const float*)d_in[21];
    const float* el_ff_W1   = (const float*)d_in[22];
    const float* el_ff_b1   = (const float*)d_in[23];
    const float* el_ff_W2   = (const float*)d_in[24];
    const float* el_ff_b2   = (const float*)d_in[25];
    const float* el_ln2_g   = (const float*)d_in[26];
    const float* el_ln2_b   = (const float*)d_in[27];
    const float* op_W       = (const float*)d_in[28];
    const float* op_b       = (const float*)d_in[29];
    const float* op_ln_g    = (const float*)d_in[30];
    const float* op_ln_b    = (const float*)d_in[31];
    float* out = (float*)d_out;

    float* base = nullptr;
    cudaGetSymbolAddress((void**)&base, g_scratch);
    uint32_t* baseW = (uint32_t*)base;

    float* maskv    = base + OFF_MASK;
    float* qkv      = base + OFF_QKV;
    float* attno    = base + OFF_ATTNO;
    float* comb     = base + OFF_COMB;
    float* mact     = base + OFF_MACT;
    float* weighted = base + OFF_WEIGHTED;
    float* sa       = base + OFF_SA;
    float* h1       = base + OFF_H1;
    float* ffo      = base + OFF_FFO;
    float* h2       = base + OFF_H2;
    float* opb      = base + OFF_OP;
    float* tab      = base + OFF_TAB;

    uint32_t* xh      = baseW + OFFW_XH;
    uint32_t* whqkv   = baseW + OFFW_WHQKV;
    uint32_t* whattn  = baseW + OFFW_WHATTN;
    uint32_t* whmix1  = baseW + OFFW_WHMIX1;
    uint32_t* whelqkv = baseW + OFFW_WHELQKV;
    uint32_t* whelout = baseW + OFFW_WHELOUT;
    uint32_t* whff1   = baseW + OFFW_WHFF1;
    uint32_t* whff2   = baseW + OFFW_WHFF2;
    uint32_t* whop    = baseW + OFFW_WHOP;
    uint32_t* attnoh  = baseW + OFFW_ATTNOH;
    uint32_t* combh   = baseW + OFFW_COMBH;
    uint32_t* weightedh = baseW + OFFW_WEIGHTEDH;
    uint32_t* h1h     = baseW + OFFW_H1H;
    uint32_t* ffh     = baseW + OFFW_FFH;
    uint32_t* h2h     = baseW + OFFW_H2H;
    uint32_t* qkvh    = baseW + OFFW_QKVH;

    cudaFuncSetAttribute(flash_kernel, cudaFuncAttributeMaxDynamicSharedMemorySize, FLASH_SMEM_BYTES);

    // 0. operand pre-convert (x + all weights)
    cvt_kernel<<<4096, 256>>>(x, qkv_W, attn_out_W, mixer_W1, el_qkv_W, el_out_W,
                              el_ff_W1, el_ff_W2, op_W, baseW);

    // 1. mask tables + fill
    {
        int nwarp = 3*2*TABENT + 3;
        int nblk = (nwarp*32 + 255) / 256;
        tab_kernel<<<nblk, 256>>>(enc_W, enc_b, enc_ln_g, enc_ln_b, tab);
        maskfill_kernel<<<(BSS + 255)/256, 256>>>(ts, tab, maskv);
    }

    // 2. per-timescale QKV (batched z=3, fp32 + half out) + fused attention + attn_out
    gemm_ca<128,0,1><<<dim3(12,16,3), 256>>>(xh, HH, whqkv, 1536, qkv_b, qkv, 1536,
                                             qkvh, 1536, HH,
                                             (size_t)0, (size_t)256*1536, (size_t)BS*1536,
                                             (size_t)BS*1536/2, (size_t)1536);
    flash_kernel<<<dim3(8, BB*NHH, 3), 128, FLASH_SMEM_BYTES>>>(qkv, qkvh, maskv, attno, attnoh);
    gemm_ca<64,0,1><<<dim3(8,16,3), 256>>>(attnoh, HH, whattn, HH, attn_out_b, comb, 1536,
                                           combh, 1536, HH,
                                           (size_t)BS*HH/2, (size_t)256*512, (size_t)HH, (size_t)HH/2, (size_t)HH);

    // 3. time mixer
    gemm_ca<64,0,0><<<dim3(8,16,1), 256>>>(combh, 1536, whmix1, HH, mixer_b1, mact, HH,
                                           baseW, 0, 1536,
                                           (size_t)0,(size_t)0,(size_t)0,(size_t)0,(size_t)0);
    ln_kernel<<<BS, 128>>>(mact, nullptr, mixer_ln_g, mixer_ln_b, mact, nullptr, 1);
    mix_kernel<<<BS, 128>>>(mact, mixer_W2, mixer_b2, comb, weighted, (__half*)weightedh);

    // 4. transformer encoder layer (post-norm)
    gemm_ca<128,0,1><<<dim3(12,16,1), 256>>>(weightedh, HH, whelqkv, 1536, el_qkv_b, qkv, 1536,
                                             qkvh, 1536, HH,
                                             (size_t)0,(size_t)0,(size_t)0,(size_t)0,(size_t)0);
    flash_kernel<<<dim3(8, BB*NHH, 1), 128, FLASH_SMEM_BYTES>>>(qkv, qkvh, nullptr, attno, attnoh);
    gemm_ca<64,0,0><<<dim3(8,16,1), 256>>>(attnoh, HH, whelout, HH, el_out_b, sa, HH,
                                           baseW, 0, HH,
                                           (size_t)0,(size_t)0,(size_t)0,(size_t)0,(size_t)0);
    ln_kernel<<<BS, 128>>>(sa, weighted, el_ln1_g, el_ln1_b, h1, (__half*)h1h, 0);
    gemm_ca<128,1,2><<<dim3(16,16,1), 256>>>(h1h, HH, whff1, 2048, el_ff_b1, nullptr, 2048,
                                             ffh, 2048, HH,
                                             (size_t)0,(size_t)0,(size_t)0,(size_t)0,(size_t)0);
    gemm_ca<64,0,0><<<dim3(8,16,1), 256>>>(ffh, 2048, whff2, HH, el_ff_b2, ffo, HH,
                                           baseW, 0, 2048,
                                           (size_t)0,(size_t)0,(size_t)0,(size_t)0,(size_t)0);
    ln_kernel<<<BS, 128>>>(ffo, h1, el_ln2_g, el_ln2_b, h2, (__half*)h2h, 0);

    // 5. output projection + LN
    gemm_ca<64,0,0><<<dim3(8,16,1), 256>>>(h2h, HH, whop, HH, op_b, opb, HH,
                                           baseW, 0, HH,
                                           (size_t)0,(size_t)0,(size_t)0,(size_t)0,(size_t)0);
    ln_kernel<<<BS, 128>>>(opb, nullptr, op_ln_g, op_ln_b, out, nullptr, 0);
}

// round 17
// speedup vs baseline: 1.2400x; 1.1690x over previous
#include <cuda_runtime.h>
#include <cuda_fp16.h>
#include <math.h>
#include <stdint.h>

// ---------------- problem constants ----------------
#define BB   4
#define SS   512
#define HH   512
#define NHH  8
#define TT   3
#define DHH  64
#define DTS  170
#define BS   (BB*SS)             // 2048
#define BSS  (BB*SS*SS)          // 1,048,576
#define EPS  1e-5f

// mask lookup table
#define NTAB   4096
#define M0MAX  5.6400f
#define TABENT (NTAB+1)
#define TABSZ  (3*2*TABENT + 3)

// ---------------- scratch layout (fp32 region, float slots) ----------------
#define OFF_MASK     ((size_t)0)
#define OFF_QKV      (OFF_MASK + (size_t)3*BSS)
#define OFF_ATTNO    (OFF_QKV + (size_t)3*BS*1536)
#define OFF_COMB     (OFF_ATTNO + (size_t)3*BS*HH)
#define OFF_MACT     (OFF_COMB + (size_t)BS*1536)
#define OFF_WEIGHTED (OFF_MACT + (size_t)BS*HH)
#define OFF_SA       (OFF_WEIGHTED + (size_t)BS*HH)
#define OFF_H1       (OFF_SA + (size_t)BS*HH)
#define OFF_FFO      (OFF_H1 + (size_t)BS*HH)
#define OFF_H2       (OFF_FFO + (size_t)BS*HH)
#define OFF_OP       (OFF_H2 + (size_t)BS*HH)
#define OFF_TAB      (OFF_OP + (size_t)BS*HH)
#define OFF_F32END   (((OFF_TAB + (size_t)TABSZ) + 3) & ~(size_t)3)

// ---------------- half region (u32 word slots) ----------------
#define OFFW_XH       OFF_F32END
#define OFFW_WHQKV    (OFFW_XH + (size_t)524288)
#define OFFW_WHATTN   (OFFW_WHQKV + (size_t)1179648)
#define OFFW_WHMIX1   (OFFW_WHATTN + (size_t)393216)
#define OFFW_WHELQKV  (OFFW_WHMIX1 + (size_t)393216)
#define OFFW_WHELOUT  (OFFW_WHELQKV + (size_t)393216)
#define OFFW_WHFF1    (OFFW_WHELOUT + (size_t)131072)
#define OFFW_WHFF2    (OFFW_WHFF1 + (size_t)524288)
#define OFFW_WHOP     (OFFW_WHFF2 + (size_t)524288)
#define OFFW_ATTNOH   (OFFW_WHOP + (size_t)131072)
#define OFFW_COMBH    (OFFW_ATTNOH + (size_t)1572864)
#define OFFW_WEIGHTEDH (OFFW_COMBH + (size_t)1572864)
#define OFFW_H1H      (OFFW_WEIGHTEDH + (size_t)524288)
#define OFFW_FFH      (OFFW_H1H + (size_t)524288)
#define OFFW_H2H      (OFFW_FFH + (size_t)2097152)
#define OFFW_QKVH     (OFFW_H2H + (size_t)524288)
#define OFFW_VHI      (OFFW_QKVH + (size_t)4718592)      // interleaved half V, 12*131072 words
#define SCRATCH_FLOATS (OFFW_VHI + (size_t)1572864)

__device__ __align__(16) float g_scratch[SCRATCH_FLOATS];

// ---------------- helpers ----------------
__device__ __forceinline__ float gelu_exact(float x) {
    return 0.5f * x * (1.0f + erff(x * 0.70710678118654752f));
}
__device__ __forceinline__ float warp_sum(float x) {
    #pragma unroll
    for (int o = 16; o > 0; o >>= 1) x += __shfl_xor_sync(0xffffffffu, x, o);
    return x;
}
__device__ __forceinline__ void mma_f16(float* c, const uint32_t* a, const uint32_t* b) {
    asm volatile(
        "mma.sync.aligned.m16n8k16.row.col.f32.f16.f16.f32 "
        "{%0,%1,%2,%3}, {%4,%5,%6,%7}, {%8,%9}, {%0,%1,%2,%3};\n"
        : "+f"(c[0]), "+f"(c[1]), "+f"(c[2]), "+f"(c[3])
        : "r"(a[0]), "r"(a[1]), "r"(a[2]), "r"(a[3]),
          "r"(b[0]), "r"(b[1]));
}
__device__ __forceinline__ uint32_t pack_h2(float lo, float hi) {
    __half2 h = __floats2half2_rn(lo, hi);
    return *reinterpret_cast<uint32_t*>(&h);
}
__device__ __forceinline__ void cp_async16(uint32_t dst, const void* src) {
    asm volatile("cp.async.ca.shared.global [%0], [%1], 16;\n" :: "r"(dst), "l"(src));
}
#define CP_COMMIT() asm volatile("cp.async.commit_group;\n" ::: "memory")
#define CP_WAIT0()  asm volatile("cp.async.wait_group 0;\n" ::: "memory")
#define CP_WAIT1()  asm volatile("cp.async.wait_group 1;\n" ::: "memory")
#define CP_WAIT2()  asm volatile("cp.async.wait_group 2;\n" ::: "memory")

// ---------------- operand pre-convert: fp32 -> half ----------------
__global__ void cvt_kernel(const float* __restrict__ x,
                           const float* __restrict__ qkvW,  const float* __restrict__ attnW,
                           const float* __restrict__ mix1W, const float* __restrict__ elqkvW,
                           const float* __restrict__ eloutW,const float* __restrict__ ff1W,
                           const float* __restrict__ ff2W,  const float* __restrict__ opW,
                           uint32_t* __restrict__ baseW)
{
    const uint32_t TOTW = 4194304u;
    for (uint32_t w = blockIdx.x*blockDim.x + threadIdx.x; w < TOTW; w += gridDim.x*blockDim.x) {
        const float* src; uint32_t rel, N; uint32_t* dst;
        if      (w < 524288u)  { src = x;      rel = w;            N = 1;    dst = baseW + OFFW_XH; }
        else if (w < 1703936u) { src = qkvW;   rel = w - 524288u;  N = 1536; dst = baseW + OFFW_WHQKV; }
        else if (w < 2097152u) { src = attnW;  rel = w - 1703936u; N = 512;  dst = baseW + OFFW_WHATTN; }
        else if (w < 2490368u) { src = mix1W;  rel = w - 2097152u; N = 512;  dst = baseW + OFFW_WHMIX1; }
        else if (w < 2883584u) { src = elqkvW; rel = w - 2490368u; N = 1536; dst = baseW + OFFW_WHELQKV; }
        else if (w < 3014656u) { src = eloutW; rel = w - 2883584u; N = 512;  dst = baseW + OFFW_WHELOUT; }
        else if (w < 3538944u) { src = ff1W;   rel = w - 3014656u; N = 2048; dst = baseW + OFFW_WHFF1; }
        else if (w < 4063232u) { src = ff2W;   rel = w - 3538944u; N = 512;  dst = baseW + OFFW_WHFF2; }
        else                   { src = opW;    rel = w - 4063232u; N = 512;  dst = baseW + OFFW_WHOP; }
        uint32_t p = rel / N, n = rel - p*N;
        dst[rel] = pack_h2(src[(size_t)(2*p)*N + n], src[(size_t)(2*p+1)*N + n]);
    }
}

// ---------------- V interleave: half qkv rows -> kv-pair-interleaved half2 words ----------------
// out[tb][p][n] = pack(V[2p][n], V[2p+1][n]) where V rows are tokens of (t,b) block.
__global__ void vintl_kernel(const uint16_t* __restrict__ qh, uint32_t* __restrict__ vhi,
                             uint32_t totw)
{
    for (uint32_t w = blockIdx.x*blockDim.x + threadIdx.x; w < totw; w += gridDim.x*blockDim.x) {
        uint32_t n  = w & 511u;
        uint32_t p  = (w >> 9) & 255u;
        uint32_t tb = w >> 17;
        size_t row0 = ((size_t)tb*512 + 2*p) * 1536 + 1024 + n;
        uint32_t h0 = qh[row0];
        uint32_t h1 = qh[row0 + 1536];
        vhi[w] = (h1 << 16) | h0;
    }
}

// ---------------- mask table build ----------------
__global__ void tab_kernel(const float* __restrict__ enc_W,
                           const float* __restrict__ enc_b,
                           const float* __restrict__ enc_g,
                           const float* __restrict__ enc_be,
                           float* __restrict__ tab)
{
    int w = (blockIdx.x * blockDim.x + threadIdx.x) >> 5;
    int lane = threadIdx.x & 31;
    const int NE = 3 * 2 * TABENT;
    if (w >= NE + 3) return;
    int i; float dir, mag;
    if (w < NE) {
        i = w / (2 * TABENT);
        int r = w - i * (2 * TABENT);
        int d = r / TABENT;
        int j = r - d * TABENT;
        dir = d ? 1.f : -1.f;
        float m0 = (float)j * (M0MAX / NTAB);
        float sc = (i == 0) ? 1.f : ((i == 1) ? 0.1f : 0.01f);
        mag = m0 * sc;
    } else {
        i = w - NE; dir = 0.f; mag = 0.f;
    }
    const float* W0 = enc_W + (size_t)(i*2+0)*DTS;
    const float* W1 = enc_W + (size_t)(i*2+1)*DTS;
    const float* bb = enc_b + (size_t)i*DTS;
    const float* gg = enc_g + (size_t)i*DTS;
    const float* be = enc_be + (size_t)i*DTS;

    float e[6];
    float s = 0.f, ss = 0.f;
    #pragma unroll
    for (int j2 = 0; j2 < 6; j2++) {
        int d = lane + 32*j2;
        float v = 0.f;
        if (d < DTS) v = dir*W0[d] + mag*W1[d] + bb[d];
        e[j2] = v; s += v; ss += v*v;
    }
    s  = warp_sum(s);
    ss = warp_sum(ss);
    float mean = s * (1.f/DTS);
    float var  = ss * (1.f/DTS) - mean*mean;
    float rs = rsqrtf(var + EPS);
    float gs = 0.f;
    #pragma unroll
    for (int j2 = 0; j2 < 6; j2++) {
        int d = lane + 32*j2;
        if (d < DTS) {
            float y = (e[j2] - mean) * rs * gg[d] + be[d];
            gs += gelu_exact(y);
        }
    }
    gs = warp_sum(gs);
    if (lane == 0) tab[w] = gs * (1.f/DTS);
}

// ---------------- mask fill via table interpolation ----------------
__global__ void maskfill_kernel(const float* __restrict__ ts,
                                const float* __restrict__ tab,
                                float* __restrict__ masks)
{
    int idx = blockIdx.x * blockDim.x + threadIdx.x;
    if (idx >= BSS) return;
    int b = idx >> 18;
    int q = (idx >> 9) & 511;
    int k = idx & 511;
    float dt = ts[(b << 9) + q] - ts[(b << 9) + k];
    if (dt == 0.f) {
        #pragma unroll
        for (int i = 0; i < TT; i++)
            masks[(size_t)i*BSS + idx] = tab[3*2*TABENT + i];
    } else {
        int d = dt > 0.f ? 1 : 0;
        float m0 = log1pf(fabsf(dt) * (1.f/3600.f));
        float t = m0 * ((float)NTAB / M0MAX);
        t = fminf(t, (float)NTAB - 1e-3f);
        int j = (int)t;
        float f = t - (float)j;
        #pragma unroll
        for (int i = 0; i < TT; i++) {
            const float* tb = tab + (size_t)(i*2 + d) * TABENT;
            float a = tb[j];
            masks[(size_t)i*BSS + idx] = a + f * (tb[j+1] - a);
        }
    }
}

// ---------------- fp16 GEMM with cp.async staging, BK=16, 4-stage (R13 proven) ----------------
// OH: 0 = fp32 C only; 1 = fp32 C + half Ch; 2 = half Ch only.
template<int BN, int GELU, int OH>
__global__ __launch_bounds__(256)
void gemm_ca(const uint32_t* __restrict__ AhW, int lda,
             const uint32_t* __restrict__ BwW, int ldbW,
             const float* __restrict__ bias0,
             float* __restrict__ C0, int ldc,
             uint32_t* __restrict__ ChW, int ldch,
             int K,
             size_t sAzW, size_t sBzW, size_t sCz, size_t sChzW, size_t sbz)
{
    constexpr int SAW = 12;
    constexpr int BNP = (BN == 128) ? 136 : 72;
    constexpr int WN  = BN / 4;
    constexpr int NT2 = WN / 8;
    constexpr int ASTGW = 128*SAW;
    constexpr int BSTGW = 8*BNP;

    __shared__ __align__(16) uint32_t sA[4*ASTGW];
    __shared__ __align__(16) uint32_t sB[4*BSTGW];

    const int tid  = threadIdx.x;
    const int lane = tid & 31;
    const int warp = tid >> 5;
    const int wm = warp & 1;
    const int wn = warp >> 1;
    const int g = lane >> 2;
    const int c = lane & 3;

    const int bm = blockIdx.y * 128;
    const int bn = blockIdx.x * BN;
    const int z  = blockIdx.z;

    const float* bias = bias0 + (size_t)z * sbz;

    const int arow = tid >> 1, ahalf = tid & 1;
    const char* aSrc = (const char*)(AhW + (size_t)z*sAzW)
                       + ((size_t)(bm + arow) * lda) * 2 + ahalf * 16;
    const uint32_t saBase = (uint32_t)__cvta_generic_to_shared(sA);
    const uint32_t sbBase = (uint32_t)__cvta_generic_to_shared(sB);
    const uint32_t aDstOff = (uint32_t)((arow*SAW + ahalf*4) * 4);

    int bbp, bch; bool bact;
    if (BN == 128) { bbp = tid >> 5; bch = tid & 31; bact = true; }
    else           { bbp = tid >> 4; bch = tid & 15; bact = (tid < 128); }
    const uint32_t* bSrc = BwW + (size_t)z*sBzW + (size_t)bbp*ldbW + bn + bch*4;
    const uint32_t bDstOff = (uint32_t)((bbp*BNP + bch*4) * 4);

    float acc[4][NT2][4];
    #pragma unroll
    for (int i = 0; i < 4; i++)
        #pragma unroll
        for (int j = 0; j < NT2; j++)
            #pragma unroll
            for (int q = 0; q < 4; q++) acc[i][j][q] = 0.f;

    auto issue = [&](int s) {
        const int stg = s & 3;
        cp_async16(saBase + (uint32_t)(stg*ASTGW*4) + aDstOff, aSrc + (size_t)s*32);
        if (bact) cp_async16(sbBase + (uint32_t)(stg*BSTGW*4) + bDstOff,
                             (const void*)(bSrc + (size_t)s*8*ldbW));
    };

    const int nstage = K / 16;
    issue(0); CP_COMMIT();
    if (nstage > 1) { issue(1); CP_COMMIT(); }
    if (nstage > 2) { issue(2); CP_COMMIT(); }

    for (int s = 0; s < nstage; s++) {
        const int rem = nstage - 1 - s;
        if (rem >= 2) { CP_WAIT2(); } else if (rem == 1) { CP_WAIT1(); } else { CP_WAIT0(); }
        __syncthreads();
        if (s + 3 < nstage) { issue(s + 3); CP_COMMIT(); }

        const int stg = s & 3;
        const uint32_t* A_ = sA + stg*ASTGW;
        const uint32_t* B_ = sB + stg*BSTGW;

        uint32_t af[4][4];
        #pragma unroll
        for (int mt = 0; mt < 4; mt++) {
            const int rb = (wm*64 + mt*16 + g)*SAW;
            af[mt][0] = A_[rb + c];
            af[mt][1] = A_[rb + 8*SAW + c];
            af[mt][2] = A_[rb + c + 4];
            af[mt][3] = A_[rb + 8*SAW + c + 4];
        }
        uint32_t bf[NT2][2];
        #pragma unroll
        for (int nt = 0; nt < NT2; nt++) {
            const int n0 = wn*WN + nt*8 + g;
            bf[nt][0] = B_[c*BNP + n0];
            bf[nt][1] = B_[(c+4)*BNP + n0];
        }
        #pragma unroll
        for (int mt = 0; mt < 4; mt++)
            #pragma unroll
            for (int nt = 0; nt < NT2; nt++)
                mma_f16(acc[mt][nt], af[mt], bf[nt]);
    }

    float* C = C0 + (size_t)z * sCz;
    uint32_t* Ch = ChW + (size_t)z * sChzW;
    #pragma unroll
    for (int mt = 0; mt < 4; mt++) {
        const int row = bm + wm*64 + mt*16 + g;
        #pragma unroll
        for (int nt = 0; nt < NT2; nt++) {
            const int col = bn + wn*WN + nt*8 + c*2;
            float2 bb = *(const float2*)(bias + col);
            float v00 = acc[mt][nt][0] + bb.x, v01 = acc[mt][nt][1] + bb.y;
            float v10 = acc[mt][nt][2] + bb.x, v11 = acc[mt][nt][3] + bb.y;
            if (GELU) {
                v00 = gelu_exact(v00); v01 = gelu_exact(v01);
                v10 = gelu_exact(v10); v11 = gelu_exact(v11);
            }
            if (OH != 2) {
                *(float2*)(C + (size_t)row*ldc + col) = make_float2(v00, v01);
                *(float2*)(C + (size_t)(row+8)*ldc + col) = make_float2(v10, v11);
            }
            if (OH >= 1) {
                Ch[((size_t)row*ldch + col) >> 1]     = pack_h2(v00, v01);
                Ch[((size_t)(row+8)*ldch + col) >> 1] = pack_h2(v10, v11);
            }
        }
    }
}

// ---------------- fused flash attention: fp16 QK^T + fp16 PV (interleaved Vh) ----------------
// smem (words): KH0 [64][36] | KH1 [64][36] (Q first) | VH [32 pairs][72]
#define KHS 36
#define KHTILE (64*KHS)            // 2304 words
#define VOFFW  (2*KHTILE)          // 4608
#define VHS 72
#define VHTILE (32*VHS)            // 2304 words
#define FLASH_SMEM_BYTES ((2*KHTILE + VHTILE)*4)   // 27648 B

__global__ __launch_bounds__(128, 4)
void flash_kernel(const uint32_t* __restrict__ qkhW,       // half qkv (Q,K rows)
                  const uint32_t* __restrict__ vhiW,       // interleaved half V [tb][256][512]
                  const float* __restrict__ maskb,
                  uint32_t* __restrict__ attnohW)
{
    extern __shared__ uint32_t fsw[];

    const int qt = blockIdx.x;
    const int bh = blockIdx.y;
    const int t  = blockIdx.z;
    const int b = bh >> 3, h = bh & 7;
    const int tid = threadIdx.x;
    const int lane = tid & 31, warp = tid >> 5;
    const int g = lane >> 2, c = lane & 3;
    const int r0 = warp*16 + g, r1 = r0 + 8;

    const size_t qbase = (size_t)t*BS*1536 + (size_t)b*SS*1536 + h*DHH;
    const uint32_t* QhW = qkhW + (qbase >> 1);
    const uint32_t* KhW = QhW + (HH >> 1);
    const uint32_t* Vhi = vhiW + ((size_t)(t*BB + b)) * 131072 + h*64;
    const float* Mp = maskb ? (maskb + (size_t)t*BSS + (size_t)b*SS*SS + (size_t)(qt*64)*SS)
                            : nullptr;
    const size_t obase = (size_t)t*BS*HH + (size_t)b*SS*HH + (size_t)(qt*64)*HH + h*DHH;
    uint32_t* OhW = attnohW + (obase >> 1);

    const int srow = tid >> 1;
    const int shalfH = (tid & 1) * 16;
    const int vrow = tid >> 2;        // 0..31 (kv pair)
    const int vchunk = tid & 3;       // 4 chunks of 4 words each, strided by 16
    const uint32_t smemBase = (uint32_t)__cvta_generic_to_shared(fsw);

    auto stageH = [&](const uint32_t* srcW, int tile, uint32_t dstTileW) {
        const uint32_t* src = srcW + (size_t)(tile*64 + srow)*768 + shalfH;
        uint32_t dst = smemBase + (dstTileW + (uint32_t)(srow*KHS + shalfH)) * 4;
        #pragma unroll
        for (int j = 0; j < 4; j++) cp_async16(dst + j*16, src + j*4);
    };
    auto stageVh = [&](int tile) {
        const uint32_t* src = Vhi + (size_t)(tile*32 + vrow)*512;
        uint32_t dst = smemBase + (uint32_t)(VOFFW + vrow*VHS) * 4;
        #pragma unroll
        for (int j = 0; j < 4; j++) {
            const int off = (vchunk + 4*j) * 4;
            cp_async16(dst + off*4, src + off);
        }
    };

    // prologue: Q -> KH1 region; K(0) -> KH0
    {
        stageH(QhW, qt, (uint32_t)KHTILE);
        stageH(KhW, 0, 0u);
        CP_COMMIT();
        CP_WAIT0();
        __syncthreads();
    }

    uint32_t qf[4][4];
    {
        const uint32_t* sQ = fsw + KHTILE;
        #pragma unroll
        for (int j = 0; j < 4; j++) {
            qf[j][0] = sQ[r0*KHS + 8*j + c];
            qf[j][1] = sQ[r1*KHS + 8*j + c];
            qf[j][2] = sQ[r0*KHS + 8*j + c + 4];
            qf[j][3] = sQ[r1*KHS + 8*j + c + 4];
        }
    }
    __syncthreads();   // Q reads done before kt=0 stages into KH1

    float of[8][4];
    #pragma unroll
    for (int nt = 0; nt < 8; nt++)
        #pragma unroll
        for (int q = 0; q < 4; q++) of[nt][q] = 0.f;
    float mA = -1e30f, lA = 0.f, mB = -1e30f, lB = 0.f;

    for (int kt = 0; kt < 8; kt++) {
        const int cur = kt & 1;
        // stage K(kt+1) into other K buffer, Vh(kt) into the single V buffer
        if (kt + 1 < 8) stageH(KhW, kt + 1, (uint32_t)((cur ^ 1)*KHTILE));
        stageVh(kt);
        CP_COMMIT();

        const uint32_t* sK = fsw + cur*KHTILE;
        const uint32_t* sVh = fsw + VOFFW;

        // ---- scores: fp16 m16n8k16 ----
        float sc[8][4];
        #pragma unroll
        for (int nt = 0; nt < 8; nt++)
            sc[nt][0] = sc[nt][1] = sc[nt][2] = sc[nt][3] = 0.f;
        #pragma unroll
        for (int j = 0; j < 4; j++) {
            #pragma unroll
            for (int nt = 0; nt < 8; nt++) {
                const uint32_t* kp = sK + (nt*8 + g)*KHS + 8*j;
                uint32_t bf[2] = { kp[c], kp[c + 4] };
                mma_f16(sc[nt], qf[j], bf);
            }
        }
        if (Mp) {
            const float* m0p = Mp + (size_t)r0*SS + kt*64 + 2*c;
            const float* m1p = Mp + (size_t)r1*SS + kt*64 + 2*c;
            #pragma unroll
            for (int nt = 0; nt < 8; nt++) {
                float2 u = *(const float2*)(m0p + nt*8);
                float2 v = *(const float2*)(m1p + nt*8);
                sc[nt][0] = sc[nt][0]*0.125f + u.x;
                sc[nt][1] = sc[nt][1]*0.125f + u.y;
                sc[nt][2] = sc[nt][2]*0.125f + v.x;
                sc[nt][3] = sc[nt][3]*0.125f + v.y;
            }
        } else {
            #pragma unroll
            for (int nt = 0; nt < 8; nt++) {
                sc[nt][0] *= 0.125f; sc[nt][1] *= 0.125f;
                sc[nt][2] *= 0.125f; sc[nt][3] *= 0.125f;
            }
        }
        // ---- online softmax ----
        float aMax = -1e30f, bMax = -1e30f;
        #pragma unroll
        for (int nt = 0; nt < 8; nt++) {
            aMax = fmaxf(aMax, fmaxf(sc[nt][0], sc[nt][1]));
            bMax = fmaxf(bMax, fmaxf(sc[nt][2], sc[nt][3]));
        }
        aMax = fmaxf(aMax, __shfl_xor_sync(0xffffffffu, aMax, 1));
        aMax = fmaxf(aMax, __shfl_xor_sync(0xffffffffu, aMax, 2));
        bMax = fmaxf(bMax, __shfl_xor_sync(0xffffffffu, bMax, 1));
        bMax = fmaxf(bMax, __shfl_xor_sync(0xffffffffu, bMax, 2));
        float mnA = fmaxf(mA, aMax), mnB = fmaxf(mB, bMax);
        float alA = __expf(mA - mnA), alB = __expf(mB - mnB);
        mA = mnA; mB = mnB;
        float sumA = 0.f, sumB = 0.f;
        #pragma unroll
        for (int nt = 0; nt < 8; nt++) {
            sc[nt][0] = __expf(sc[nt][0] - mnA); sumA += sc[nt][0];
            sc[nt][1] = __expf(sc[nt][1] - mnA); sumA += sc[nt][1];
            sc[nt][2] = __expf(sc[nt][2] - mnB); sumB += sc[nt][2];
            sc[nt][3] = __expf(sc[nt][3] - mnB); sumB += sc[nt][3];
        }
        sumA += __shfl_xor_sync(0xffffffffu, sumA, 1);
        sumA += __shfl_xor_sync(0xffffffffu, sumA, 2);
        sumB += __shfl_xor_sync(0xffffffffu, sumB, 1);
        sumB += __shfl_xor_sync(0xffffffffu, sumB, 2);
        lA = lA*alA + sumA;
        lB = lB*alB + sumB;
        #pragma unroll
        for (int nt = 0; nt < 8; nt++) {
            of[nt][0] *= alA; of[nt][1] *= alA;
            of[nt][2] *= alB; of[nt][3] *= alB;
        }

        // Vh(kt) (and K(kt+1)) must have landed; make them visible to all warps
        CP_WAIT0();
        __syncthreads();

        // ---- PV: fp16 m16n8k16; P packed straight from sc accumulators ----
        #pragma unroll
        for (int j = 0; j < 4; j++) {
            uint32_t af[4] = {
                pack_h2(sc[2*j][0],   sc[2*j][1]),
                pack_h2(sc[2*j][2],   sc[2*j][3]),
                pack_h2(sc[2*j+1][0], sc[2*j+1][1]),
                pack_h2(sc[2*j+1][2], sc[2*j+1][3])
            };
            #pragma unroll
            for (int nt = 0; nt < 8; nt++) {
                const uint32_t* vp = sVh + (8*j + c)*VHS + nt*8 + g;
                uint32_t bf[2] = { vp[0], vp[4*VHS] };
                mma_f16(of[nt], af, bf);
            }
        }
        __syncthreads();   // all warps done with Vh before next stageVh
    }

    const float invA = 1.f / lA, invB = 1.f / lB;
    #pragma unroll
    for (int nt = 0; nt < 8; nt++) {
        const int col = nt*8 + 2*c;
        OhW[((size_t)r0*HH + col) >> 1] = pack_h2(of[nt][0]*invA, of[nt][1]*invA);
        OhW[((size_t)r1*HH + col) >> 1] = pack_h2(of[nt][2]*invB, of[nt][3]*invB);
    }
}

// ---------------- LayerNorm over 512 (+residual, +gelu, +optional half copy) ----------------
__global__ void ln_kernel(const float* __restrict__ in, const float* __restrict__ res,
                          const float* __restrict__ g, const float* __restrict__ be,
                          float* __restrict__ out, __half* __restrict__ outh, int do_gelu)
{
    __shared__ float red[4];
    int row = blockIdx.x, tid = threadIdx.x;
    const float* ip = in + (size_t)row*HH;
    const float* rp = res ? (res + (size_t)row*HH) : nullptr;
    float v[4]; float s = 0.f;
    #pragma unroll
    for (int j = 0; j < 4; j++) {
        float x = ip[tid + 128*j];
        if (rp) x += rp[tid + 128*j];
        v[j] = x; s += x;
    }
    s = warp_sum(s);
    if ((tid & 31) == 0) red[tid >> 5] = s;
    __syncthreads();
    float mean = (red[0]+red[1]+red[2]+red[3]) * (1.f/HH);
    __syncthreads();
    float ss = 0.f;
    #pragma unroll
    for (int j = 0; j < 4; j++) { float d = v[j] - mean; ss += d*d; }
    ss = warp_sum(ss);
    if ((tid & 31) == 0) red[tid >> 5] = ss;
    __syncthreads();
    float var = (red[0]+red[1]+red[2]+red[3]) * (1.f/HH);
    float rs = rsqrtf(var + EPS);
    float* op = out + (size_t)row*HH;
    __half* oh = outh ? (outh + (size_t)row*HH) : nullptr;
    #pragma unroll
    for (int j = 0; j < 4; j++) {
        int cc = tid + 128*j;
        float y = (v[j] - mean) * rs * g[cc] + be[cc];
        if (do_gelu) y = gelu_exact(y);
        op[cc] = y;
        if (oh) oh[cc] = __float2half_rn(y);
    }
}

// ---------------- mixer ----------------
__global__ void mix_kernel(const float* __restrict__ mact, const float* __restrict__ W2,
                           const float* __restrict__ b2, const float* __restrict__ comb,
                           float* __restrict__ weighted, __half* __restrict__ weightedh)
{
    __shared__ float sl[3][4];
    __shared__ float smix[3];
    int row = blockIdx.x, tid = threadIdx.x;
    const float* mrow = mact + (size_t)row*HH;
    float l0 = 0.f, l1 = 0.f, l2 = 0.f;
    for (int d = tid; d < HH; d += 128) {
        float m = mrow[d];
        l0 += m * W2[d*3+0];
        l1 += m * W2[d*3+1];
        l2 += m * W2[d*3+2];
    }
    l0 = warp_sum(l0); l1 = warp_sum(l1); l2 = warp_sum(l2);
    int w = tid >> 5;
    if ((tid & 31) == 0) { sl[0][w] = l0; sl[1][w] = l1; sl[2][w] = l2; }
    __syncthreads();
    if (tid == 0) {
        float a0 = sl[0][0]+sl[0][1]+sl[0][2]+sl[0][3] + b2[0];
        float a1 = sl[1][0]+sl[1][1]+sl[1][2]+sl[1][3] + b2[1];
        float a2 = sl[2][0]+sl[2][1]+sl[2][2]+sl[2][3] + b2[2];
        float mx = fmaxf(a0, fmaxf(a1, a2));
        float e0 = expf(a0-mx), e1 = expf(a1-mx), e2 = expf(a2-mx);
        float inv = 1.f / (e0+e1+e2);
        smix[0] = e0*inv; smix[1] = e1*inv; smix[2] = e2*inv;
    }
    __syncthreads();
    float m0 = smix[0], m1 = smix[1], m2 = smix[2];
    const float* crow = comb + (size_t)row*(3*HH);
    float* wrow = weighted + (size_t)row*HH;
    __half* whrow = weightedh + (size_t)row*HH;
    for (int cc = tid; cc < HH; cc += 128) {
        float v = m0*crow[cc] + m1*crow[HH + cc] + m2*crow[2*HH + cc];
        wrow[cc] = v;
        whrow[cc] = __float2half_rn(v);
    }
}

// ---------------- launch ----------------
extern "C" void kernel_launch(void* const* d_in, const int* in_sizes, int n_in,
                              void* d_out, int out_size)
{
    const float* x          = (const float*)d_in[0];
    const float* ts         = (const float*)d_in[1];
    const float* enc_W      = (const float*)d_in[2];
    const float* enc_b      = (const float*)d_in[3];
    const float* enc_ln_g   = (const float*)d_in[4];
    const float* enc_ln_b   = (const float*)d_in[5];
    const float* qkv_W      = (const float*)d_in[6];
    const float* qkv_b      = (const float*)d_in[7];
    const float* attn_out_W = (const float*)d_in[8];
    const float* attn_out_b = (const float*)d_in[9];
    const float* mixer_W1   = (const float*)d_in[10];
    const float* mixer_b1   = (const float*)d_in[11];
    const float* mixer_ln_g = (const float*)d_in[12];
    const float* mixer_ln_b = (const float*)d_in[13];
    const float* mixer_W2   = (const float*)d_in[14];
    const float* mixer_b2   = (const float*)d_in[15];
    const float* el_qkv_W   = (const float*)d_in[16];
    const float* el_qkv_b   = (const float*)d_in[17];
    const float* el_out_W   = (const float*)d_in[18];
    const float* el_out_b   = (const float*)d_in[19];
    const float* el_ln1_g   = (const float*)d_in[20];
    const float* el_ln1_b   = (const float*)d_in[21];
    const float* el_ff_W1   = (const float*)d_in[22];
    const float* el_ff_b1   = (const float*)d_in[23];
    const float* el_ff_W2   = (const float*)d_in[24];
    const float* el_ff_b2   = (const float*)d_in[25];
    const float* el_ln2_g   = (const float*)d_in[26];
    const float* el_ln2_b   = (const float*)d_in[27];
    const float* op_W       = (const float*)d_in[28];
    const float* op_b       = (const float*)d_in[29];
    const float* op_ln_g    = (const float*)d_in[30];
    const float* op_ln_b    = (const float*)d_in[31];
    float* out = (float*)d_out;

    float* base = nullptr;
    cudaGetSymbolAddress((void**)&base, g_scratch);
    uint32_t* baseW = (uint32_t*)base;

    float* maskv    = base + OFF_MASK;
    float* comb     = base + OFF_COMB;
    float* mact     = base + OFF_MACT;
    float* weighted = base + OFF_WEIGHTED;
    float* sa       = base + OFF_SA;
    float* h1       = base + OFF_H1;
    float* ffo      = base + OFF_FFO;
    float* h2       = base + OFF_H2;
    float* opb      = base + OFF_OP;
    float* tab      = base + OFF_TAB;

    uint32_t* xh      = baseW + OFFW_XH;
    uint32_t* whqkv   = baseW + OFFW_WHQKV;
    uint32_t* whattn  = baseW + OFFW_WHATTN;
    uint32_t* whmix1  = baseW + OFFW_WHMIX1;
    uint32_t* whelqkv = baseW + OFFW_WHELQKV;
    uint32_t* whelout = baseW + OFFW_WHELOUT;
    uint32_t* whff1   = baseW + OFFW_WHFF1;
    uint32_t* whff2   = baseW + OFFW_WHFF2;
    uint32_t* whop    = baseW + OFFW_WHOP;
    uint32_t* attnoh  = baseW + OFFW_ATTNOH;
    uint32_t* combh   = baseW + OFFW_COMBH;
    uint32_t* weightedh = baseW + OFFW_WEIGHTEDH;
    uint32_t* h1h     = baseW + OFFW_H1H;
    uint32_t* ffh     = baseW + OFFW_FFH;
    uint32_t* h2h     = baseW + OFFW_H2H;
    uint32_t* qkvh    = baseW + OFFW_QKVH;
    uint32_t* vhi     = baseW + OFFW_VHI;

    cudaFuncSetAttribute(flash_kernel, cudaFuncAttributeMaxDynamicSharedMemorySize, FLASH_SMEM_BYTES);

    // 0. operand pre-convert (x + all weights)
    cvt_kernel<<<4096, 256>>>(x, qkv_W, attn_out_W, mixer_W1, el_qkv_W, el_out_W,
                              el_ff_W1, el_ff_W2, op_W, baseW);

    // 1. mask tables + fill
    {
        int nwarp = 3*2*TABENT + 3;
        int nblk = (nwarp*32 + 255) / 256;
        tab_kernel<<<nblk, 256>>>(enc_W, enc_b, enc_ln_g, enc_ln_b, tab);
        maskfill_kernel<<<(BSS + 255)/256, 256>>>(ts, tab, maskv);
    }

    // 2. per-timescale QKV (batched z=3, half only) + V interleave + fused attention + attn_out
    gemm_ca<128,0,2><<<dim3(12,16,3), 256>>>(xh, HH, whqkv, 1536, qkv_b, nullptr, 1536,
                                             qkvh, 1536, HH,
                                             (size_t)0, (size_t)256*1536, (size_t)0,
                                             (size_t)BS*1536/2, (size_t)1536);
    vintl_kernel<<<6144, 256>>>((const uint16_t*)qkvh, vhi, 1572864u);
    flash_kernel<<<dim3(8, BB*NHH, 3), 128, FLASH_SMEM_BYTES>>>(qkvh, vhi, maskv, attnoh);
    gemm_ca<64,0,1><<<dim3(8,16,3), 256>>>(attnoh, HH, whattn, HH, attn_out_b, comb, 1536,
                                           combh, 1536, HH,
                                           (size_t)BS*HH/2, (size_t)256*512, (size_t)HH, (size_t)HH/2, (size_t)HH);

    // 3. time mixer
    gemm_ca<64,0,0><<<dim3(8,16,1), 256>>>(combh, 1536, whmix1, HH, mixer_b1, mact, HH,
                                           baseW, 0, 1536,
                                           (size_t)0,(size_t)0,(size_t)0,(size_t)0,(size_t)0);
    ln_kernel<<<BS, 128>>>(mact, nullptr, mixer_ln_g, mixer_ln_b, mact, nullptr, 1);
    mix_kernel<<<BS, 128>>>(mact, mixer_W2, mixer_b2, comb, weighted, (__half*)weightedh);

    // 4. transformer encoder layer (post-norm)
    gemm_ca<128,0,2><<<dim3(12,16,1), 256>>>(weightedh, HH, whelqkv, 1536, el_qkv_b, nullptr, 1536,
                                             qkvh, 1536, HH,
                                             (size_t)0,(size_t)0,(size_t)0,(size_t)0,(size_t)0);
    vintl_kernel<<<2048, 256>>>((const uint16_t*)qkvh, vhi, 524288u);
    flash_kernel<<<dim3(8, BB*NHH, 1), 128, FLASH_SMEM_BYTES>>>(qkvh, vhi, nullptr, attnoh);
    gemm_ca<64,0,0><<<dim3(8,16,1), 256>>>(attnoh, HH, whelout, HH, el_out_b, sa, HH,
                                           baseW, 0, HH,
                                           (size_t)0,(size_t)0,(size_t)0,(size_t)0,(size_t)0);
    ln_kernel<<<BS, 128>>>(sa, weighted, el_ln1_g, el_ln1_b, h1, (__half*)h1h, 0);
    gemm_ca<128,1,2><<<dim3(16,16,1), 256>>>(h1h, HH, whff1, 2048, el_ff_b1, nullptr, 2048,
                                             ffh, 2048, HH,
                                             (size_t)0,(size_t)0,(size_t)0,(size_t)0,(size_t)0);
    gemm_ca<64,0,0><<<dim3(8,16,1), 256>>>(ffh, 2048, whff2, HH, el_ff_b2, ffo, HH,
                                           baseW, 0, 2048,
                                           (size_t)0,(size_t)0,(size_t)0,(size_t)0,(size_t)0);
    ln_kernel<<<BS, 128>>>(ffo, h1, el_ln2_g, el_ln2_b, h2, (__half*)h2h, 0);

    // 5. output projection + LN
    gemm_ca<64,0,0><<<dim3(8,16,1), 256>>>(h2h, HH, whop, HH, op_b, opb, HH,
                                           baseW, 0, HH,
                                           (size_t)0,(size_t)0,(size_t)0,(size_t)0,(size_t)0);
    ln_kernel<<<BS, 128>>>(opb, nullptr, op_ln_g, op_ln_b, out, nullptr, 0);
}